// round 1
// baseline (speedup 1.0000x reference)
#include <cuda_runtime.h>
#include <math.h>
#include <stdint.h>

// Problem constants (fixed shapes)
#define LQ   4096
#define CDIM 128
#define KNN  128
#define NH   4
#define DH   32
#define CP   16

// Scratch (allocation-free rule: __device__ globals)
__device__ float g_a [LQ*CDIM];
__device__ float g_q [LQ*CDIM];
__device__ float g_k [LQ*CDIM];
__device__ float g_v [LQ*CDIM];
__device__ float g_g [LQ*CDIM];
__device__ float g_ao[LQ*CDIM];

// ---- packed f32x2 FMA (FFMA2: only reachable via PTX) ----
#define PACK2(dst, lo, hi) \
    asm("mov.b64 %0, {%1,%2};" : "=l"(dst) : "f"(lo), "f"(hi))
#define UNPACK2(lo, hi, src) \
    asm("mov.b64 {%0,%1}, %2;" : "=f"(lo), "=f"(hi) : "l"(src))
#define FMA2(acc, a, b) \
    asm("fma.rn.f32x2 %0, %1, %2, %0;" : "+l"(acc) : "l"(a), "l"(b))

// ============================================================
// K0: a = rms(Q_L, ln1_w).  One warp per row.
// ============================================================
__global__ void __launch_bounds__(256) rms_in_kernel(
    const float* __restrict__ X, const float* __restrict__ w)
{
    int row  = blockIdx.x * 8 + (threadIdx.x >> 5);
    int lane = threadIdx.x & 31;
    float4 x = ((const float4*)(X + (size_t)row * CDIM))[lane];
    float ss = x.x*x.x + x.y*x.y + x.z*x.z + x.w*x.w;
    #pragma unroll
    for (int o = 16; o; o >>= 1) ss += __shfl_xor_sync(0xffffffffu, ss, o);
    float s = rsqrtf(ss * (1.0f / CDIM) + 1e-5f);
    float4 wv = ((const float4*)w)[lane];
    float4 o;
    o.x = x.x * s * wv.x; o.y = x.y * s * wv.y;
    o.z = x.z * s * wv.z; o.w = x.w * s * wv.w;
    ((float4*)(g_a + (size_t)row * CDIM))[lane] = o;
}

// ============================================================
// GEMM core: C[128x128] tile = A[rowBase:+128, 0:128] @ W^T
// (out[m,n] = sum_k A[m,k] * W[n,k]).  256 thr, 8x8 micro, f32x2.
// Ast/Bst: k-major [32][132].
// ============================================================
__device__ __forceinline__ void gemm_core(
    const float* __restrict__ A, const float* __restrict__ W,
    int rowBase, float* Ast, float* Bst, float c[8][8])
{
    const int tid = threadIdx.x;
    const int tx = tid & 15, ty = tid >> 4;

    unsigned long long acc[8][4];
    #pragma unroll
    for (int i = 0; i < 8; i++)
        #pragma unroll
        for (int p = 0; p < 4; p++) acc[i][p] = 0ull;

    for (int kc = 0; kc < CDIM; kc += 32) {
        #pragma unroll
        for (int i = 0; i < 4; i++) {
            int l4 = tid + i * 256;          // 0..1023
            int r  = l4 >> 3;                // 0..127
            int kq = l4 & 7;                 // float4 slot in 32-wide chunk
            float4 av = *(const float4*)(A + (size_t)(rowBase + r) * CDIM + kc + kq * 4);
            Ast[(kq*4+0)*132 + r] = av.x;
            Ast[(kq*4+1)*132 + r] = av.y;
            Ast[(kq*4+2)*132 + r] = av.z;
            Ast[(kq*4+3)*132 + r] = av.w;
            float4 bv = *(const float4*)(W + (size_t)r * CDIM + kc + kq * 4);
            Bst[(kq*4+0)*132 + r] = bv.x;
            Bst[(kq*4+1)*132 + r] = bv.y;
            Bst[(kq*4+2)*132 + r] = bv.z;
            Bst[(kq*4+3)*132 + r] = bv.w;
        }
        __syncthreads();
        #pragma unroll
        for (int kk = 0; kk < 32; kk++) {
            float4 a0 = *(const float4*)&Ast[kk*132 + ty*8];
            float4 a1 = *(const float4*)&Ast[kk*132 + ty*8 + 4];
            const unsigned long long* bp =
                (const unsigned long long*)&Bst[kk*132 + tx*8];
            unsigned long long b0 = bp[0], b1 = bp[1], b2 = bp[2], b3 = bp[3];
            float ar[8] = {a0.x,a0.y,a0.z,a0.w,a1.x,a1.y,a1.z,a1.w};
            #pragma unroll
            for (int i = 0; i < 8; i++) {
                unsigned long long a2; PACK2(a2, ar[i], ar[i]);
                FMA2(acc[i][0], a2, b0);
                FMA2(acc[i][1], a2, b1);
                FMA2(acc[i][2], a2, b2);
                FMA2(acc[i][3], a2, b3);
            }
        }
        __syncthreads();
    }
    #pragma unroll
    for (int i = 0; i < 8; i++)
        #pragma unroll
        for (int p = 0; p < 4; p++)
            UNPACK2(c[i][2*p], c[i][2*p+1], acc[i][p]);
}

// ============================================================
// K1: qkvg = a @ [Wq;Wk;Wv;Wg]^T with fused epilogues.
// grid (32 row-tiles, 4 matrices). midx: 0=q(rms), 1=k(rms),
// 2=v(plain), 3=g(sigmoid)
// ============================================================
__global__ void __launch_bounds__(256) qkvg_kernel(
    const float* __restrict__ Wq, const float* __restrict__ Wk,
    const float* __restrict__ Wv, const float* __restrict__ Wg,
    const float* __restrict__ lnq, const float* __restrict__ lnk)
{
    __shared__ float Ast[32*132];
    __shared__ float Bst[32*132];
    __shared__ float red[128*17];
    __shared__ float rowscale[128];

    const int midx = blockIdx.y;
    const float* W = (midx == 0) ? Wq : (midx == 1) ? Wk : (midx == 2) ? Wv : Wg;
    const int rowBase = blockIdx.x * 128;

    float c[8][8];
    gemm_core(g_a, W, rowBase, Ast, Bst, c);

    const int tx = threadIdx.x & 15, ty = threadIdx.x >> 4;

    if (midx < 2) {
        // row-wise RMSNorm over the full 128-col row (this block owns it)
        #pragma unroll
        for (int i = 0; i < 8; i++) {
            float ss = 0.f;
            #pragma unroll
            for (int j = 0; j < 8; j++) ss += c[i][j] * c[i][j];
            red[(ty*8 + i)*17 + tx] = ss;
        }
        __syncthreads();
        if (threadIdx.x < 128) {
            float s = 0.f;
            #pragma unroll
            for (int p = 0; p < 16; p++) s += red[threadIdx.x*17 + p];
            rowscale[threadIdx.x] = rsqrtf(s * (1.0f / CDIM) + 1e-5f);
        }
        __syncthreads();
        const float* lnw = (midx == 0) ? lnq : lnk;
        float lw[8];
        #pragma unroll
        for (int j = 0; j < 8; j++) lw[j] = lnw[tx*8 + j];
        float* out = (midx == 0) ? g_q : g_k;
        #pragma unroll
        for (int i = 0; i < 8; i++) {
            float s = rowscale[ty*8 + i];
            float4 o0, o1;
            o0.x = c[i][0]*s*lw[0]; o0.y = c[i][1]*s*lw[1];
            o0.z = c[i][2]*s*lw[2]; o0.w = c[i][3]*s*lw[3];
            o1.x = c[i][4]*s*lw[4]; o1.y = c[i][5]*s*lw[5];
            o1.z = c[i][6]*s*lw[6]; o1.w = c[i][7]*s*lw[7];
            float* op = out + (size_t)(rowBase + ty*8 + i) * CDIM + tx*8;
            *(float4*)op       = o0;
            *(float4*)(op + 4) = o1;
        }
    } else if (midx == 2) {
        #pragma unroll
        for (int i = 0; i < 8; i++) {
            float4 o0 = {c[i][0], c[i][1], c[i][2], c[i][3]};
            float4 o1 = {c[i][4], c[i][5], c[i][6], c[i][7]};
            float* op = g_v + (size_t)(rowBase + ty*8 + i) * CDIM + tx*8;
            *(float4*)op       = o0;
            *(float4*)(op + 4) = o1;
        }
    } else {
        #pragma unroll
        for (int i = 0; i < 8; i++) {
            float o[8];
            #pragma unroll
            for (int j = 0; j < 8; j++) o[j] = 1.0f / (1.0f + __expf(-c[i][j]));
            float4 o0 = {o[0], o[1], o[2], o[3]};
            float4 o1 = {o[4], o[5], o[6], o[7]};
            float* op = g_g + (size_t)(rowBase + ty*8 + i) * CDIM + tx*8;
            *(float4*)op       = o0;
            *(float4*)(op + 4) = o1;
        }
    }
}

// ============================================================
// K2: attention. One block (256 thr) per query row l.
//  - gather P_LL rows -> pair bias (4 heads)
//  - gathered QK^T scores + bias, softmax, AV, sigmoid gate
// ============================================================
__global__ void __launch_bounds__(256) attn_kernel(
    const float* __restrict__ P, const int* __restrict__ idxg,
    const float* __restrict__ Wb)
{
    __shared__ int   idx_s[KNN];
    __shared__ float q_s[CDIM];
    __shared__ float wb_s[NH*CP];
    __shared__ float sc[NH][KNN];
    __shared__ float av_red[2][CDIM];

    const int l = blockIdx.x;
    const int t = threadIdx.x;

    // Phase 1: load indices, q (pre-scaled by 1/sqrt(dh)), Wb
    if (t < KNN) {
        idx_s[t] = idxg[(size_t)l * KNN + t];
        q_s[t]   = g_q[(size_t)l * CDIM + t] * 0.17677669529663687f; // 1/sqrt(32)
    }
    if (t < NH*CP) wb_s[t] = Wb[t];
    __syncthreads();

    // Phase 2: pair bias: sc[h][j] = P[l, idx_j, :16] . Wb[h,:]
    if (t < KNN) {
        const float4* pr = (const float4*)(P + ((size_t)l * LQ + idx_s[t]) * CP);
        float4 p0 = pr[0], p1 = pr[1], p2 = pr[2], p3 = pr[3];
        float pv[16] = {p0.x,p0.y,p0.z,p0.w, p1.x,p1.y,p1.z,p1.w,
                        p2.x,p2.y,p2.z,p2.w, p3.x,p3.y,p3.z,p3.w};
        #pragma unroll
        for (int h = 0; h < NH; h++) {
            float b = 0.f;
            #pragma unroll
            for (int p = 0; p < CP; p++) b += pv[p] * wb_s[h*CP + p];
            sc[h][t] = b;
        }
    }
    __syncthreads();

    // Phase 3: scores. warp w handles keys j = w*16 .. w*16+15.
    {
        const int w = t >> 5, lane = t & 31;
        const int head = lane >> 3;
        float4 qf = *(const float4*)&q_s[lane * 4];
        #pragma unroll 4
        for (int jj = 0; jj < 16; jj++) {
            int j = (w << 4) | jj;
            float4 kv = ((const float4*)(g_k + (size_t)idx_s[j] * CDIM))[lane];
            float d = qf.x*kv.x + qf.y*kv.y + qf.z*kv.z + qf.w*kv.w;
            d += __shfl_down_sync(0xffffffffu, d, 4, 8);
            d += __shfl_down_sync(0xffffffffu, d, 2, 8);
            d += __shfl_down_sync(0xffffffffu, d, 1, 8);
            if ((lane & 7) == 0) sc[head][j] += d;
        }
    }
    __syncthreads();

    // Phase 4: softmax per head (warps 0..3)
    if (t < 128) {
        int h = t >> 5, lane = t & 31;
        float s0 = sc[h][lane], s1 = sc[h][lane+32],
              s2 = sc[h][lane+64], s3 = sc[h][lane+96];
        float mx = fmaxf(fmaxf(s0, s1), fmaxf(s2, s3));
        #pragma unroll
        for (int o = 16; o; o >>= 1) mx = fmaxf(mx, __shfl_xor_sync(0xffffffffu, mx, o));
        float e0 = __expf(s0 - mx), e1 = __expf(s1 - mx),
              e2 = __expf(s2 - mx), e3 = __expf(s3 - mx);
        float sum = e0 + e1 + e2 + e3;
        #pragma unroll
        for (int o = 16; o; o >>= 1) sum += __shfl_xor_sync(0xffffffffu, sum, o);
        float inv = 1.0f / sum;
        sc[h][lane]    = e0 * inv;
        sc[h][lane+32] = e1 * inv;
        sc[h][lane+64] = e2 * inv;
        sc[h][lane+96] = e3 * inv;
    }
    __syncthreads();

    // Phase 5: AV. 256 threads = 2 halves x 128 dims.
    {
        const int d = t & 127, half = t >> 7;
        const int h = d >> 5;
        float acc = 0.f;
        const int j0 = half * 64;
        #pragma unroll 8
        for (int jj = 0; jj < 64; jj++) {
            int j = j0 + jj;
            acc += sc[h][j] * g_v[(size_t)idx_s[j] * CDIM + d];
        }
        av_red[half][d] = acc;
    }
    __syncthreads();
    if (t < CDIM) {
        float o = (av_red[0][t] + av_red[1][t]) * g_g[(size_t)l * CDIM + t];
        g_ao[(size_t)l * CDIM + t] = o;
    }
}

// ============================================================
// K3: out = g_ao @ Wo^T
// ============================================================
__global__ void __launch_bounds__(256) out_gemm_kernel(
    const float* __restrict__ Wo, float* __restrict__ out)
{
    __shared__ float Ast[32*132];
    __shared__ float Bst[32*132];

    const int rowBase = blockIdx.x * 128;
    float c[8][8];
    gemm_core(g_ao, Wo, rowBase, Ast, Bst, c);

    const int tx = threadIdx.x & 15, ty = threadIdx.x >> 4;
    #pragma unroll
    for (int i = 0; i < 8; i++) {
        float4 o0 = {c[i][0], c[i][1], c[i][2], c[i][3]};
        float4 o1 = {c[i][4], c[i][5], c[i][6], c[i][7]};
        float* op = out + (size_t)(rowBase + ty*8 + i) * CDIM + tx*8;
        *(float4*)op       = o0;
        *(float4*)(op + 4) = o1;
    }
}

// ============================================================
extern "C" void kernel_launch(void* const* d_in, const int* in_sizes, int n_in,
                              void* d_out, int out_size)
{
    const float* Q_L  = (const float*)d_in[0];
    const float* P    = (const float*)d_in[1];
    const int*   idx  = (const int*)  d_in[2];
    const float* Wq   = (const float*)d_in[3];
    const float* Wk   = (const float*)d_in[4];
    const float* Wv   = (const float*)d_in[5];
    const float* Wg   = (const float*)d_in[6];
    const float* Wb   = (const float*)d_in[7];
    const float* Wo   = (const float*)d_in[8];
    const float* ln1  = (const float*)d_in[9];
    const float* lnq  = (const float*)d_in[10];
    const float* lnk  = (const float*)d_in[11];
    float* out = (float*)d_out;

    rms_in_kernel<<<LQ/8, 256>>>(Q_L, ln1);
    dim3 g1(LQ/128, 4);
    qkvg_kernel<<<g1, 256>>>(Wq, Wk, Wv, Wg, lnq, lnk);
    attn_kernel<<<LQ, 256>>>(P, idx, Wb);
    out_gemm_kernel<<<LQ/128, 256>>>(Wo, out);
}

// round 2
// speedup vs baseline: 1.2511x; 1.2511x over previous
#include <cuda_runtime.h>
#include <cuda_fp16.h>
#include <math.h>
#include <stdint.h>

#define LQ   4096
#define CDIM 128
#define KNN  128
#define NH   4
#define DH   32
#define CP   16

// Scratch (__device__ globals; no allocation allowed)
__device__ float  g_q [LQ*CDIM];
__device__ __half g_kh[LQ*CDIM];
__device__ __half g_vh[LQ*CDIM];
__device__ float  g_g [LQ*CDIM];
__device__ float  g_ao[LQ*CDIM];

// ---- packed f32x2 FMA ----
#define PACK2(dst, lo, hi) \
    asm("mov.b64 %0, {%1,%2};" : "=l"(dst) : "f"(lo), "f"(hi))
#define UNPACK2(lo, hi, src) \
    asm("mov.b64 {%0,%1}, %2;" : "=f"(lo), "=f"(hi) : "l"(src))
#define FMA2(acc, a, b) \
    asm("fma.rn.f32x2 %0, %1, %2, %0;" : "+l"(acc) : "l"(a), "l"(b))

// ============================================================
// GEMM core: 32x128 tile, K=128. A already staged k-major in
// Ast[128][36].  B (weights, [128][128] row-major, out = A@W^T)
// streamed in 32-k chunks into Bst[32][132].
// 256 thr: ty=warp(0..7)->4 rows, tx=lane(0..31)->4 cols.
// ============================================================
__device__ __forceinline__ void gemm32_core(
    const float* __restrict__ W, const float* Ast, float* Bst, float c[4][4])
{
    const int tid = threadIdx.x;
    const int tx = tid & 31, ty = tid >> 5;

    unsigned long long acc[4][2];
    #pragma unroll
    for (int i = 0; i < 4; i++) { acc[i][0] = 0ull; acc[i][1] = 0ull; }

    const int nW = tid >> 1;          // 0..127 (weight row)
    const int qq = tid & 1;           // which 16-k half

    for (int kc = 0; kc < CDIM; kc += 32) {
        // load B chunk: W[n][kc+qq*16 .. +16) -> Bst[k'][n]
        {
            const float* wp = W + (size_t)nW * CDIM + kc + qq * 16;
            #pragma unroll
            for (int f = 0; f < 4; f++) {
                float4 bv = *(const float4*)(wp + f * 4);
                int kk = qq * 16 + f * 4;
                Bst[(kk+0)*132 + nW] = bv.x;
                Bst[(kk+1)*132 + nW] = bv.y;
                Bst[(kk+2)*132 + nW] = bv.z;
                Bst[(kk+3)*132 + nW] = bv.w;
            }
        }
        __syncthreads();
        #pragma unroll
        for (int kk = 0; kk < 32; kk++) {
            float4 a4 = *(const float4*)&Ast[(kc + kk) * 36 + ty * 4]; // broadcast
            ulonglong2 b4 = *(const ulonglong2*)&Bst[kk * 132 + tx * 4];
            float ar[4] = {a4.x, a4.y, a4.z, a4.w};
            #pragma unroll
            for (int i = 0; i < 4; i++) {
                unsigned long long aa; PACK2(aa, ar[i], ar[i]);
                FMA2(acc[i][0], aa, b4.x);
                FMA2(acc[i][1], aa, b4.y);
            }
        }
        __syncthreads();
    }
    #pragma unroll
    for (int i = 0; i < 4; i++) {
        UNPACK2(c[i][0], c[i][1], acc[i][0]);
        UNPACK2(c[i][2], c[i][3], acc[i][1]);
    }
}

// ============================================================
// K1: fused rms(Q_L) + {q,k,v,g} projection + epilogues.
// grid (128 row-tiles, 4 matrices). 32 rows per CTA.
// midx: 0=q(rms,fp32) 1=k(rms,fp16) 2=v(fp16) 3=g(sigmoid,fp32)
// ============================================================
__global__ void __launch_bounds__(256) qkvg_kernel(
    const float* __restrict__ Q_L,
    const float* __restrict__ Wq, const float* __restrict__ Wk,
    const float* __restrict__ Wv, const float* __restrict__ Wg,
    const float* __restrict__ ln1,
    const float* __restrict__ lnq, const float* __restrict__ lnk)
{
    __shared__ __align__(16) float Ast[128*36];
    __shared__ __align__(16) float Bst[32*132];

    const int midx = blockIdx.y;
    const float* W = (midx == 0) ? Wq : (midx == 1) ? Wk : (midx == 2) ? Wv : Wg;
    const int rowBase = blockIdx.x * 32;
    const int tid = threadIdx.x;

    // --- stage A = rms(Q_L rows) into Ast (k-major), 8 thr/row ---
    {
        int r  = tid >> 3;          // 0..31
        int q8 = tid & 7;           // 16-float segment
        const float* xp = Q_L + (size_t)(rowBase + r) * CDIM + q8 * 16;
        float4 x0 = ((const float4*)xp)[0];
        float4 x1 = ((const float4*)xp)[1];
        float4 x2 = ((const float4*)xp)[2];
        float4 x3 = ((const float4*)xp)[3];
        float ss = x0.x*x0.x + x0.y*x0.y + x0.z*x0.z + x0.w*x0.w
                 + x1.x*x1.x + x1.y*x1.y + x1.z*x1.z + x1.w*x1.w
                 + x2.x*x2.x + x2.y*x2.y + x2.z*x2.z + x2.w*x2.w
                 + x3.x*x3.x + x3.y*x3.y + x3.z*x3.z + x3.w*x3.w;
        #pragma unroll
        for (int o = 4; o; o >>= 1) ss += __shfl_xor_sync(0xffffffffu, ss, o);
        float s = rsqrtf(ss * (1.0f / CDIM) + 1e-5f);
        float xv[16] = {x0.x,x0.y,x0.z,x0.w, x1.x,x1.y,x1.z,x1.w,
                        x2.x,x2.y,x2.z,x2.w, x3.x,x3.y,x3.z,x3.w};
        #pragma unroll
        for (int f = 0; f < 16; f++) {
            int k = q8 * 16 + f;
            Ast[k * 36 + r] = xv[f] * s * ln1[k];
        }
    }
    __syncthreads();

    float c[4][4];
    gemm32_core(W, Ast, Bst, c);

    const int tx = tid & 31, ty = tid >> 5;
    const int row = rowBase + ty * 4;     // rows ty*4 .. ty*4+3? No:
    // each warp (ty) owns rows rowBase+ty*4+i — wait: m = ty*4+i
    // (32 rows via 8 warps x 4)

    if (midx < 2) {
        const float* lnw = (midx == 0) ? lnq : lnk;
        float lw[4];
        #pragma unroll
        for (int j = 0; j < 4; j++) lw[j] = lnw[tx * 4 + j];
        #pragma unroll
        for (int i = 0; i < 4; i++) {
            float ss = c[i][0]*c[i][0] + c[i][1]*c[i][1]
                     + c[i][2]*c[i][2] + c[i][3]*c[i][3];
            #pragma unroll
            for (int o = 16; o; o >>= 1) ss += __shfl_xor_sync(0xffffffffu, ss, o);
            float s = rsqrtf(ss * (1.0f / CDIM) + 1e-5f);
            float o0 = c[i][0]*s*lw[0], o1 = c[i][1]*s*lw[1];
            float o2 = c[i][2]*s*lw[2], o3 = c[i][3]*s*lw[3];
            size_t off = (size_t)(rowBase + ty*4 + i) * CDIM + tx*4;
            if (midx == 0) {
                float4 ov = {o0, o1, o2, o3};
                *(float4*)(g_q + off) = ov;
            } else {
                __half2 h0 = __floats2half2_rn(o0, o1);
                __half2 h1 = __floats2half2_rn(o2, o3);
                uint2 u; u.x = *(unsigned*)&h0; u.y = *(unsigned*)&h1;
                *(uint2*)(g_kh + off) = u;
            }
        }
    } else if (midx == 2) {
        #pragma unroll
        for (int i = 0; i < 4; i++) {
            __half2 h0 = __floats2half2_rn(c[i][0], c[i][1]);
            __half2 h1 = __floats2half2_rn(c[i][2], c[i][3]);
            uint2 u; u.x = *(unsigned*)&h0; u.y = *(unsigned*)&h1;
            *(uint2*)(g_vh + (size_t)(rowBase + ty*4 + i) * CDIM + tx*4) = u;
        }
    } else {
        #pragma unroll
        for (int i = 0; i < 4; i++) {
            float4 ov;
            ov.x = 1.0f / (1.0f + __expf(-c[i][0]));
            ov.y = 1.0f / (1.0f + __expf(-c[i][1]));
            ov.z = 1.0f / (1.0f + __expf(-c[i][2]));
            ov.w = 1.0f / (1.0f + __expf(-c[i][3]));
            *(float4*)(g_g + (size_t)(rowBase + ty*4 + i) * CDIM + tx*4) = ov;
        }
    }
}

// ============================================================
// K2: attention. One block (256 thr) per query row l.
// P-gather (DRAM) and K-gather (L2) overlap: bias and scores go
// to separate smem arrays, combined in softmax.
// ============================================================
__global__ void __launch_bounds__(256) attn_kernel(
    const float* __restrict__ P, const int* __restrict__ idxg,
    const float* __restrict__ Wb)
{
    __shared__ int   idx_s[KNN];
    __shared__ float q_s[CDIM];
    __shared__ float wb_s[NH*CP];
    __shared__ float bias_s[NH][KNN];
    __shared__ float sc[NH][KNN];
    __shared__ float av_red[4][CDIM];

    const int l = blockIdx.x;
    const int t = threadIdx.x;
    const int w = t >> 5, lane = t & 31;

    // Phase 1: indices, q (pre-scaled 1/sqrt(dh)), Wb
    if (t < KNN) {
        idx_s[t] = idxg[(size_t)l * KNN + t];
        q_s[t]   = g_q[(size_t)l * CDIM + t] * 0.17677669529663687f;
    }
    if (t < NH*CP) wb_s[t] = Wb[t];
    __syncthreads();

    // Phase 2: pair bias (warp w: keys j0..j0+15; 2 lanes per key)
    {
        int j  = (w << 4) + (lane >> 1);
        int pp = lane & 1;                 // 8-float half of the P row
        const float* pr = P + ((size_t)l * LQ + idx_s[j]) * CP + pp * 8;
        float4 p0 = ((const float4*)pr)[0];
        float4 p1 = ((const float4*)pr)[1];
        float pv[8] = {p0.x,p0.y,p0.z,p0.w, p1.x,p1.y,p1.z,p1.w};
        float b[NH];
        #pragma unroll
        for (int h = 0; h < NH; h++) {
            const float* wbp = &wb_s[h*CP + pp*8];
            b[h] = pv[0]*wbp[0] + pv[1]*wbp[1] + pv[2]*wbp[2] + pv[3]*wbp[3]
                 + pv[4]*wbp[4] + pv[5]*wbp[5] + pv[6]*wbp[6] + pv[7]*wbp[7];
        }
        #pragma unroll
        for (int h = 0; h < NH; h++) {
            b[h] += __shfl_xor_sync(0xffffffffu, b[h], 1);
            if (pp == 0) bias_s[h][j] = b[h];
        }
    }

    // Phase 3: scores (warp w: keys j0..j0+15, fp16 K)
    {
        const int head = lane >> 3;
        float4 qf = *(const float4*)&q_s[lane * 4];
        #pragma unroll 4
        for (int jj = 0; jj < 16; jj++) {
            int j = (w << 4) | jj;
            uint2 ku = ((const uint2*)(g_kh + (size_t)idx_s[j] * CDIM))[lane];
            float2 k0 = __half22float2(*(__half2*)&ku.x);
            float2 k1 = __half22float2(*(__half2*)&ku.y);
            float d = qf.x*k0.x + qf.y*k0.y + qf.z*k1.x + qf.w*k1.y;
            d += __shfl_down_sync(0xffffffffu, d, 4, 8);
            d += __shfl_down_sync(0xffffffffu, d, 2, 8);
            d += __shfl_down_sync(0xffffffffu, d, 1, 8);
            if ((lane & 7) == 0) sc[head][j] = d;
        }
    }
    __syncthreads();

    // Phase 4: softmax per head (warps 0..3), combining dot + bias
    if (t < 128) {
        int h = w;
        float s0 = sc[h][lane]    + bias_s[h][lane];
        float s1 = sc[h][lane+32] + bias_s[h][lane+32];
        float s2 = sc[h][lane+64] + bias_s[h][lane+64];
        float s3 = sc[h][lane+96] + bias_s[h][lane+96];
        float mx = fmaxf(fmaxf(s0, s1), fmaxf(s2, s3));
        #pragma unroll
        for (int o = 16; o; o >>= 1) mx = fmaxf(mx, __shfl_xor_sync(0xffffffffu, mx, o));
        float e0 = __expf(s0 - mx), e1 = __expf(s1 - mx),
              e2 = __expf(s2 - mx), e3 = __expf(s3 - mx);
        float sum = e0 + e1 + e2 + e3;
        #pragma unroll
        for (int o = 16; o; o >>= 1) sum += __shfl_xor_sync(0xffffffffu, sum, o);
        float inv = 1.0f / sum;
        sc[h][lane]    = e0 * inv;
        sc[h][lane+32] = e1 * inv;
        sc[h][lane+64] = e2 * inv;
        sc[h][lane+96] = e3 * inv;
    }
    __syncthreads();

    // Phase 5: AV (fp16 V). 256 thr = 64 half2-dims x 4 j-groups.
    {
        const int d2 = t & 63;     // half2 index: dims 2*d2, 2*d2+1
        const int jg = t >> 6;     // j-group (32 keys each)
        const int h  = d2 >> 4;
        float ax = 0.f, ay = 0.f;
        const unsigned* vbase = (const unsigned*)g_vh;
        #pragma unroll 8
        for (int jj = 0; jj < 32; jj++) {
            int j = jg * 32 + jj;
            unsigned vu = vbase[(size_t)idx_s[j] * (CDIM/2) + d2];
            float2 vf = __half22float2(*(__half2*)&vu);
            float p = sc[h][j];
            ax += p * vf.x;
            ay += p * vf.y;
        }
        av_red[jg][2*d2]   = ax;
        av_red[jg][2*d2+1] = ay;
    }
    __syncthreads();
    if (t < CDIM) {
        float o = (av_red[0][t] + av_red[1][t] + av_red[2][t] + av_red[3][t])
                  * g_g[(size_t)l * CDIM + t];
        g_ao[(size_t)l * CDIM + t] = o;
    }
}

// ============================================================
// K3: out = g_ao @ Wo^T (32-row tiles, 128 CTAs)
// ============================================================
__global__ void __launch_bounds__(256) out_gemm_kernel(
    const float* __restrict__ Wo, float* __restrict__ out)
{
    __shared__ __align__(16) float Ast[128*36];
    __shared__ __align__(16) float Bst[32*132];

    const int rowBase = blockIdx.x * 32;
    const int tid = threadIdx.x;

    // stage A = g_ao tile (k-major)
    {
        int r  = tid >> 3;
        int q8 = tid & 7;
        const float* xp = g_ao + (size_t)(rowBase + r) * CDIM + q8 * 16;
        #pragma unroll
        for (int f = 0; f < 4; f++) {
            float4 x = ((const float4*)xp)[f];
            int k = q8 * 16 + f * 4;
            Ast[(k+0)*36 + r] = x.x;
            Ast[(k+1)*36 + r] = x.y;
            Ast[(k+2)*36 + r] = x.z;
            Ast[(k+3)*36 + r] = x.w;
        }
    }
    __syncthreads();

    float c[4][4];
    gemm32_core(Wo, Ast, Bst, c);

    const int tx = tid & 31, ty = tid >> 5;
    #pragma unroll
    for (int i = 0; i < 4; i++) {
        float4 ov = {c[i][0], c[i][1], c[i][2], c[i][3]};
        *(float4*)(out + (size_t)(rowBase + ty*4 + i) * CDIM + tx*4) = ov;
    }
}

// ============================================================
extern "C" void kernel_launch(void* const* d_in, const int* in_sizes, int n_in,
                              void* d_out, int out_size)
{
    const float* Q_L  = (const float*)d_in[0];
    const float* P    = (const float*)d_in[1];
    const int*   idx  = (const int*)  d_in[2];
    const float* Wq   = (const float*)d_in[3];
    const float* Wk   = (const float*)d_in[4];
    const float* Wv   = (const float*)d_in[5];
    const float* Wg   = (const float*)d_in[6];
    const float* Wb   = (const float*)d_in[7];
    const float* Wo   = (const float*)d_in[8];
    const float* ln1  = (const float*)d_in[9];
    const float* lnq  = (const float*)d_in[10];
    const float* lnk  = (const float*)d_in[11];
    float* out = (float*)d_out;

    dim3 g1(LQ/32, 4);
    qkvg_kernel<<<g1, 256>>>(Q_L, Wq, Wk, Wv, Wg, ln1, lnq, lnk);
    attn_kernel<<<LQ, 256>>>(P, idx, Wb);
    out_gemm_kernel<<<LQ/32, 256>>>(Wo, out);
}

// round 3
// speedup vs baseline: 1.2613x; 1.0082x over previous
#include <cuda_runtime.h>
#include <cuda_fp16.h>
#include <math.h>
#include <stdint.h>

#define LQ   4096
#define CDIM 128
#define KNN  128
#define NH   4
#define DH   32
#define CP   16

__device__ float  g_q [LQ*CDIM];
__device__ __half g_kh[LQ*CDIM];
__device__ __half g_vh[LQ*CDIM];
__device__ float  g_g [LQ*CDIM];
__device__ float  g_ao[LQ*CDIM];

typedef unsigned long long ull;

#define PACK2(dst, lo, hi) \
    asm("mov.b64 %0, {%1,%2};" : "=l"(dst) : "f"(lo), "f"(hi))
#define UNPACK2(lo, hi, src) \
    asm("mov.b64 {%0,%1}, %2;" : "=f"(lo), "=f"(hi) : "l"(src))
#define FMA2(acc, a, b) \
    asm("fma.rn.f32x2 %0, %1, %2, %0;" : "+l"(acc) : "l"(a), "l"(b))

// ============================================================
// GEMM core: C[64x128] tile = A @ W^T, K=128.
// Ast: k-major [128][64], pre-staged (rows r in tile).
// Bst: [16][128] streamed in 16-k chunks from W (row-major
// [128][128], out[m,n] = sum_k A[m,k]*W[n,k]).
// 256 thr: ty=warp(0..7) -> 8 rows (4 row-PAIRS), tx=lane -> 4 cols.
// Row-pair accumulators: acc[p][j] = {c[2p][j], c[2p+1][j]}.
// ============================================================
__device__ __forceinline__ void gemm64_core(
    const float* __restrict__ W, const float* Ast, float* Bst, float c[8][4])
{
    const int tid = threadIdx.x;
    const int tx = tid & 31, ty = tid >> 5;
    const int nW = tid >> 1;          // weight row (output col) 0..127
    const int qq = tid & 1;           // 8-k half of chunk

    ull acc[4][4];
    #pragma unroll
    for (int p = 0; p < 4; p++)
        #pragma unroll
        for (int j = 0; j < 4; j++) acc[p][j] = 0ull;

    for (int kc = 0; kc < CDIM; kc += 16) {
        // stage B chunk: W[nW][kc+qq*8 .. +8) -> Bst[k'][nW]
        {
            const float* wp = W + (size_t)nW * CDIM + kc + qq * 8;
            float4 b0 = ((const float4*)wp)[0];
            float4 b1 = ((const float4*)wp)[1];
            int kb = qq * 8;
            Bst[(kb+0)*128 + nW] = b0.x;
            Bst[(kb+1)*128 + nW] = b0.y;
            Bst[(kb+2)*128 + nW] = b0.z;
            Bst[(kb+3)*128 + nW] = b0.w;
            Bst[(kb+4)*128 + nW] = b1.x;
            Bst[(kb+5)*128 + nW] = b1.y;
            Bst[(kb+6)*128 + nW] = b1.z;
            Bst[(kb+7)*128 + nW] = b1.w;
        }
        __syncthreads();
        #pragma unroll
        for (int kk = 0; kk < 16; kk++) {
            // A: 8 rows = 4 natural 64-bit row-pairs (broadcast)
            const ulonglong2* ap =
                (const ulonglong2*)&Ast[(kc + kk) * 64 + ty * 8];
            ulonglong2 a01 = ap[0];   // {r0,r1},{r2,r3}
            ulonglong2 a23 = ap[1];   // {r4,r5},{r6,r7}
            float4 bv = *(const float4*)&Bst[kk * 128 + tx * 4];
            ull bb0, bb1, bb2, bb3;
            PACK2(bb0, bv.x, bv.x);
            PACK2(bb1, bv.y, bv.y);
            PACK2(bb2, bv.z, bv.z);
            PACK2(bb3, bv.w, bv.w);
            FMA2(acc[0][0], a01.x, bb0); FMA2(acc[0][1], a01.x, bb1);
            FMA2(acc[0][2], a01.x, bb2); FMA2(acc[0][3], a01.x, bb3);
            FMA2(acc[1][0], a01.y, bb0); FMA2(acc[1][1], a01.y, bb1);
            FMA2(acc[1][2], a01.y, bb2); FMA2(acc[1][3], a01.y, bb3);
            FMA2(acc[2][0], a23.x, bb0); FMA2(acc[2][1], a23.x, bb1);
            FMA2(acc[2][2], a23.x, bb2); FMA2(acc[2][3], a23.x, bb3);
            FMA2(acc[3][0], a23.y, bb0); FMA2(acc[3][1], a23.y, bb1);
            FMA2(acc[3][2], a23.y, bb2); FMA2(acc[3][3], a23.y, bb3);
        }
        __syncthreads();
    }
    #pragma unroll
    for (int p = 0; p < 4; p++)
        #pragma unroll
        for (int j = 0; j < 4; j++)
            UNPACK2(c[2*p][j], c[2*p+1][j], acc[p][j]);
}

// ============================================================
// K1: fused rms(Q_L) + {q,k,v,g} projection + epilogues.
// grid (64 row-tiles, 4 matrices), 64 rows per CTA.
// ============================================================
__global__ void __launch_bounds__(256) qkvg_kernel(
    const float* __restrict__ Q_L,
    const float* __restrict__ Wq, const float* __restrict__ Wk,
    const float* __restrict__ Wv, const float* __restrict__ Wg,
    const float* __restrict__ ln1,
    const float* __restrict__ lnq, const float* __restrict__ lnk)
{
    __shared__ __align__(16) float Ast[128*64];
    __shared__ __align__(16) float Bst[16*128];
    __shared__ float red[64][4];

    const int midx = blockIdx.y;
    const float* W = (midx == 0) ? Wq : (midx == 1) ? Wk : (midx == 2) ? Wv : Wg;
    const int rowBase = blockIdx.x * 64;
    const int tid = threadIdx.x;

    // stage A = rms(Q_L rows) into Ast (k-major), 4 thr/row
    {
        int r    = tid & 63;
        int half = tid >> 6;           // 32-k segment
        const float* xp = Q_L + (size_t)(rowBase + r) * CDIM + half * 32;
        float4 x[8];
        #pragma unroll
        for (int f = 0; f < 8; f++) x[f] = ((const float4*)xp)[f];
        float ss = 0.f;
        #pragma unroll
        for (int f = 0; f < 8; f++)
            ss += x[f].x*x[f].x + x[f].y*x[f].y + x[f].z*x[f].z + x[f].w*x[f].w;
        red[r][half] = ss;
        __syncthreads();
        float sa = red[r][0] + red[r][1] + red[r][2] + red[r][3];
        float s = rsqrtf(sa * (1.0f / CDIM) + 1e-5f);
        #pragma unroll
        for (int f = 0; f < 8; f++) {
            int k = half * 32 + f * 4;
            Ast[(k+0)*64 + r] = x[f].x * s * __ldg(ln1 + k + 0);
            Ast[(k+1)*64 + r] = x[f].y * s * __ldg(ln1 + k + 1);
            Ast[(k+2)*64 + r] = x[f].z * s * __ldg(ln1 + k + 2);
            Ast[(k+3)*64 + r] = x[f].w * s * __ldg(ln1 + k + 3);
        }
    }
    __syncthreads();

    float c[8][4];
    gemm64_core(W, Ast, Bst, c);

    const int tx = tid & 31, ty = tid >> 5;

    if (midx < 2) {
        const float* lnw = (midx == 0) ? lnq : lnk;
        float lw[4];
        #pragma unroll
        for (int j = 0; j < 4; j++) lw[j] = lnw[tx * 4 + j];
        #pragma unroll
        for (int i = 0; i < 8; i++) {
            float ss = c[i][0]*c[i][0] + c[i][1]*c[i][1]
                     + c[i][2]*c[i][2] + c[i][3]*c[i][3];
            #pragma unroll
            for (int o = 16; o; o >>= 1)
                ss += __shfl_xor_sync(0xffffffffu, ss, o);
            float s = rsqrtf(ss * (1.0f / CDIM) + 1e-5f);
            float o0 = c[i][0]*s*lw[0], o1 = c[i][1]*s*lw[1];
            float o2 = c[i][2]*s*lw[2], o3 = c[i][3]*s*lw[3];
            size_t off = (size_t)(rowBase + ty*8 + i) * CDIM + tx*4;
            if (midx == 0) {
                float4 ov = {o0, o1, o2, o3};
                *(float4*)(g_q + off) = ov;
            } else {
                __half2 h0 = __floats2half2_rn(o0, o1);
                __half2 h1 = __floats2half2_rn(o2, o3);
                uint2 u; u.x = *(unsigned*)&h0; u.y = *(unsigned*)&h1;
                *(uint2*)(g_kh + off) = u;
            }
        }
    } else if (midx == 2) {
        #pragma unroll
        for (int i = 0; i < 8; i++) {
            __half2 h0 = __floats2half2_rn(c[i][0], c[i][1]);
            __half2 h1 = __floats2half2_rn(c[i][2], c[i][3]);
            uint2 u; u.x = *(unsigned*)&h0; u.y = *(unsigned*)&h1;
            *(uint2*)(g_vh + (size_t)(rowBase + ty*8 + i) * CDIM + tx*4) = u;
        }
    } else {
        #pragma unroll
        for (int i = 0; i < 8; i++) {
            float4 ov;
            ov.x = 1.0f / (1.0f + __expf(-c[i][0]));
            ov.y = 1.0f / (1.0f + __expf(-c[i][1]));
            ov.z = 1.0f / (1.0f + __expf(-c[i][2]));
            ov.w = 1.0f / (1.0f + __expf(-c[i][3]));
            *(float4*)(g_g + (size_t)(rowBase + ty*8 + i) * CDIM + tx*4) = ov;
        }
    }
}

// ============================================================
// K2: attention. One block (256 thr) per query row l.
// ============================================================
__global__ void __launch_bounds__(256) attn_kernel(
    const float* __restrict__ P, const int* __restrict__ idxg,
    const float* __restrict__ Wb)
{
    __shared__ int   idx_s[KNN];
    __shared__ float q_s[CDIM];
    __shared__ float wb_s[NH*CP];
    __shared__ float bias_s[NH][KNN];
    __shared__ float sc[NH][KNN];
    __shared__ float av_red[4][CDIM];

    const int l = blockIdx.x;
    const int t = threadIdx.x;
    const int w = t >> 5, lane = t & 31;

    if (t < KNN) {
        idx_s[t] = idxg[(size_t)l * KNN + t];
        q_s[t]   = g_q[(size_t)l * CDIM + t] * 0.17677669529663687f;
    }
    if (t < NH*CP) wb_s[t] = Wb[t];
    __syncthreads();

    // pair bias (warp w: keys j0..j0+15; 2 lanes per key)
    {
        int j  = (w << 4) + (lane >> 1);
        int pp = lane & 1;
        const float* pr = P + ((size_t)l * LQ + idx_s[j]) * CP + pp * 8;
        float4 p0 = ((const float4*)pr)[0];
        float4 p1 = ((const float4*)pr)[1];
        float pv[8] = {p0.x,p0.y,p0.z,p0.w, p1.x,p1.y,p1.z,p1.w};
        float b[NH];
        #pragma unroll
        for (int h = 0; h < NH; h++) {
            const float* wbp = &wb_s[h*CP + pp*8];
            b[h] = pv[0]*wbp[0] + pv[1]*wbp[1] + pv[2]*wbp[2] + pv[3]*wbp[3]
                 + pv[4]*wbp[4] + pv[5]*wbp[5] + pv[6]*wbp[6] + pv[7]*wbp[7];
        }
        #pragma unroll
        for (int h = 0; h < NH; h++) {
            b[h] += __shfl_xor_sync(0xffffffffu, b[h], 1);
            if (pp == 0) bias_s[h][j] = b[h];
        }
    }

    // scores (warp w: keys j0..j0+15, fp16 K)
    {
        const int head = lane >> 3;
        float4 qf = *(const float4*)&q_s[lane * 4];
        #pragma unroll 4
        for (int jj = 0; jj < 16; jj++) {
            int j = (w << 4) | jj;
            uint2 ku = ((const uint2*)(g_kh + (size_t)idx_s[j] * CDIM))[lane];
            float2 k0 = __half22float2(*(__half2*)&ku.x);
            float2 k1 = __half22float2(*(__half2*)&ku.y);
            float d = qf.x*k0.x + qf.y*k0.y + qf.z*k1.x + qf.w*k1.y;
            d += __shfl_down_sync(0xffffffffu, d, 4, 8);
            d += __shfl_down_sync(0xffffffffu, d, 2, 8);
            d += __shfl_down_sync(0xffffffffu, d, 1, 8);
            if ((lane & 7) == 0) sc[head][j] = d;
        }
    }
    __syncthreads();

    // softmax per head (warps 0..3)
    if (t < 128) {
        int h = w;
        float s0 = sc[h][lane]    + bias_s[h][lane];
        float s1 = sc[h][lane+32] + bias_s[h][lane+32];
        float s2 = sc[h][lane+64] + bias_s[h][lane+64];
        float s3 = sc[h][lane+96] + bias_s[h][lane+96];
        float mx = fmaxf(fmaxf(s0, s1), fmaxf(s2, s3));
        #pragma unroll
        for (int o = 16; o; o >>= 1) mx = fmaxf(mx, __shfl_xor_sync(0xffffffffu, mx, o));
        float e0 = __expf(s0 - mx), e1 = __expf(s1 - mx),
              e2 = __expf(s2 - mx), e3 = __expf(s3 - mx);
        float sum = e0 + e1 + e2 + e3;
        #pragma unroll
        for (int o = 16; o; o >>= 1) sum += __shfl_xor_sync(0xffffffffu, sum, o);
        float inv = 1.0f / sum;
        sc[h][lane]    = e0 * inv;
        sc[h][lane+32] = e1 * inv;
        sc[h][lane+64] = e2 * inv;
        sc[h][lane+96] = e3 * inv;
    }
    __syncthreads();

    // AV (fp16 V)
    {
        const int d2 = t & 63;
        const int jg = t >> 6;
        const int h  = d2 >> 4;
        float ax = 0.f, ay = 0.f;
        const unsigned* vbase = (const unsigned*)g_vh;
        #pragma unroll 8
        for (int jj = 0; jj < 32; jj++) {
            int j = jg * 32 + jj;
            unsigned vu = vbase[(size_t)idx_s[j] * (CDIM/2) + d2];
            float2 vf = __half22float2(*(__half2*)&vu);
            float p = sc[h][j];
            ax += p * vf.x;
            ay += p * vf.y;
        }
        av_red[jg][2*d2]   = ax;
        av_red[jg][2*d2+1] = ay;
    }
    __syncthreads();
    if (t < CDIM) {
        float o = (av_red[0][t] + av_red[1][t] + av_red[2][t] + av_red[3][t])
                  * g_g[(size_t)l * CDIM + t];
        g_ao[(size_t)l * CDIM + t] = o;
    }
}

// ============================================================
// K3: out = g_ao @ Wo^T  (64-row tiles)
// ============================================================
__global__ void __launch_bounds__(256) out_gemm_kernel(
    const float* __restrict__ Wo, float* __restrict__ out)
{
    __shared__ __align__(16) float Ast[128*64];
    __shared__ __align__(16) float Bst[16*128];

    const int rowBase = blockIdx.x * 64;
    const int tid = threadIdx.x;

    {
        int r    = tid & 63;
        int half = tid >> 6;
        const float* xp = g_ao + (size_t)(rowBase + r) * CDIM + half * 32;
        #pragma unroll
        for (int f = 0; f < 8; f++) {
            float4 x = ((const float4*)xp)[f];
            int k = half * 32 + f * 4;
            Ast[(k+0)*64 + r] = x.x;
            Ast[(k+1)*64 + r] = x.y;
            Ast[(k+2)*64 + r] = x.z;
            Ast[(k+3)*64 + r] = x.w;
        }
    }
    __syncthreads();

    float c[8][4];
    gemm64_core(Wo, Ast, Bst, c);

    const int tx = tid & 31, ty = tid >> 5;
    #pragma unroll
    for (int i = 0; i < 8; i++) {
        float4 ov = {c[i][0], c[i][1], c[i][2], c[i][3]};
        *(float4*)(out + (size_t)(rowBase + ty*8 + i) * CDIM + tx*4) = ov;
    }
}

// ============================================================
extern "C" void kernel_launch(void* const* d_in, const int* in_sizes, int n_in,
                              void* d_out, int out_size)
{
    const float* Q_L  = (const float*)d_in[0];
    const float* P    = (const float*)d_in[1];
    const int*   idx  = (const int*)  d_in[2];
    const float* Wq   = (const float*)d_in[3];
    const float* Wk   = (const float*)d_in[4];
    const float* Wv   = (const float*)d_in[5];
    const float* Wg   = (const float*)d_in[6];
    const float* Wb   = (const float*)d_in[7];
    const float* Wo   = (const float*)d_in[8];
    const float* ln1  = (const float*)d_in[9];
    const float* lnq  = (const float*)d_in[10];
    const float* lnk  = (const float*)d_in[11];
    float* out = (float*)d_out;

    dim3 g1(LQ/64, 4);
    qkvg_kernel<<<g1, 256>>>(Q_L, Wq, Wk, Wv, Wg, ln1, lnq, lnk);
    attn_kernel<<<LQ, 256>>>(P, idx, Wb);
    out_gemm_kernel<<<LQ/64, 256>>>(Wo, out);
}

// round 4
// speedup vs baseline: 1.4655x; 1.1618x over previous
#include <cuda_runtime.h>
#include <cuda_fp16.h>
#include <math.h>
#include <stdint.h>

#define LQ   4096
#define CDIM 128
#define KNN  128
#define NH   4
#define DH   32
#define CP   16

__device__ float  g_q [LQ*CDIM];
__device__ __half g_kh[LQ*CDIM];
__device__ __half g_vh[LQ*CDIM];
__device__ float  g_g [LQ*CDIM];
__device__ float  g_ao[LQ*CDIM];

typedef unsigned long long ull;

#define PACK2(dst, lo, hi) \
    asm("mov.b64 %0, {%1,%2};" : "=l"(dst) : "f"(lo), "f"(hi))
#define UNPACK2(lo, hi, src) \
    asm("mov.b64 {%0,%1}, %2;" : "=f"(lo), "=f"(hi) : "l"(src))
#define FMA2(acc, a, b) \
    asm("fma.rn.f32x2 %0, %1, %2, %0;" : "+l"(acc) : "l"(a), "l"(b))

#define BSTRIDE 132

// ------------------------------------------------------------
// Stage full W [128][128] row-major -> Bst[k][n] (k-major,
// stride 132). 256 threads, no syncs needed inside.
// ------------------------------------------------------------
__device__ __forceinline__ void stage_B(const float* __restrict__ W, float* Bst)
{
    const int tid = threadIdx.x;
    const int nW = tid >> 1;
    const int qq = tid & 1;
    #pragma unroll
    for (int kc = 0; kc < CDIM; kc += 16) {
        const float* wp = W + (size_t)nW * CDIM + kc + qq * 8;
        float4 b0 = ((const float4*)wp)[0];
        float4 b1 = ((const float4*)wp)[1];
        int kb = kc + qq * 8;
        Bst[(kb+0)*BSTRIDE + nW] = b0.x;
        Bst[(kb+1)*BSTRIDE + nW] = b0.y;
        Bst[(kb+2)*BSTRIDE + nW] = b0.z;
        Bst[(kb+3)*BSTRIDE + nW] = b0.w;
        Bst[(kb+4)*BSTRIDE + nW] = b1.x;
        Bst[(kb+5)*BSTRIDE + nW] = b1.y;
        Bst[(kb+6)*BSTRIDE + nW] = b1.z;
        Bst[(kb+7)*BSTRIDE + nW] = b1.w;
    }
}

// ------------------------------------------------------------
// Barrier-free mainloop: C[ROWS x 128], ROWS rows per CTA,
// NP row-pairs per warp (ROWS = 8*2*NP). Ast k-major stride ROWS.
// ------------------------------------------------------------
template<int ROWS, int NP>
__device__ __forceinline__ void gemm_main(
    const float* Ast, const float* Bst, float c[2*NP][4])
{
    const int tid = threadIdx.x;
    const int tx = tid & 31, ty = tid >> 5;

    ull acc[NP][4];
    #pragma unroll
    for (int p = 0; p < NP; p++)
        #pragma unroll
        for (int j = 0; j < 4; j++) acc[p][j] = 0ull;

    #pragma unroll 8
    for (int kk = 0; kk < CDIM; kk++) {
        const ull* ap = (const ull*)&Ast[kk * ROWS + ty * (2*NP)];
        float4 bv = *(const float4*)&Bst[kk * BSTRIDE + tx * 4];
        ull bb0, bb1, bb2, bb3;
        PACK2(bb0, bv.x, bv.x);
        PACK2(bb1, bv.y, bv.y);
        PACK2(bb2, bv.z, bv.z);
        PACK2(bb3, bv.w, bv.w);
        #pragma unroll
        for (int p = 0; p < NP; p++) {
            ull ap2 = ap[p];
            FMA2(acc[p][0], ap2, bb0);
            FMA2(acc[p][1], ap2, bb1);
            FMA2(acc[p][2], ap2, bb2);
            FMA2(acc[p][3], ap2, bb3);
        }
    }
    #pragma unroll
    for (int p = 0; p < NP; p++)
        #pragma unroll
        for (int j = 0; j < 4; j++)
            UNPACK2(c[2*p][j], c[2*p+1][j], acc[p][j]);
}

// ============================================================
// K1: fused rms(Q_L) + {q,k,v,g} projection + epilogues.
// grid (64 row-tiles, 4 matrices), 64 rows per CTA.
// dyn smem: Ast[128*64] + Bst[128*132]
// ============================================================
__global__ void __launch_bounds__(256) qkvg_kernel(
    const float* __restrict__ Q_L,
    const float* __restrict__ Wq, const float* __restrict__ Wk,
    const float* __restrict__ Wv, const float* __restrict__ Wg,
    const float* __restrict__ ln1,
    const float* __restrict__ lnq, const float* __restrict__ lnk)
{
    extern __shared__ __align__(16) float sm[];
    float* Ast = sm;                  // 128*64
    float* Bst = sm + 128*64;         // 128*132
    __shared__ float red[64][4];

    const int midx = blockIdx.y;
    const float* W = (midx == 0) ? Wq : (midx == 1) ? Wk : (midx == 2) ? Wv : Wg;
    const int rowBase = blockIdx.x * 64;
    const int tid = threadIdx.x;

    // stage A = rms(Q_L rows) k-major, 4 thr/row
    {
        int r    = tid & 63;
        int half = tid >> 6;
        const float* xp = Q_L + (size_t)(rowBase + r) * CDIM + half * 32;
        float4 x[8];
        #pragma unroll
        for (int f = 0; f < 8; f++) x[f] = ((const float4*)xp)[f];
        float ss = 0.f;
        #pragma unroll
        for (int f = 0; f < 8; f++)
            ss += x[f].x*x[f].x + x[f].y*x[f].y + x[f].z*x[f].z + x[f].w*x[f].w;
        red[r][half] = ss;
        stage_B(W, Bst);              // overlap W staging with rms reduce
        __syncthreads();
        float sa = red[r][0] + red[r][1] + red[r][2] + red[r][3];
        float s = rsqrtf(sa * (1.0f / CDIM) + 1e-5f);
        #pragma unroll
        for (int f = 0; f < 8; f++) {
            int k = half * 32 + f * 4;
            Ast[(k+0)*64 + r] = x[f].x * s * __ldg(ln1 + k + 0);
            Ast[(k+1)*64 + r] = x[f].y * s * __ldg(ln1 + k + 1);
            Ast[(k+2)*64 + r] = x[f].z * s * __ldg(ln1 + k + 2);
            Ast[(k+3)*64 + r] = x[f].w * s * __ldg(ln1 + k + 3);
        }
    }
    __syncthreads();

    float c[8][4];
    gemm_main<64, 4>(Ast, Bst, c);

    const int tx = tid & 31, ty = tid >> 5;

    if (midx < 2) {
        const float* lnw = (midx == 0) ? lnq : lnk;
        float lw[4];
        #pragma unroll
        for (int j = 0; j < 4; j++) lw[j] = lnw[tx * 4 + j];
        #pragma unroll
        for (int i = 0; i < 8; i++) {
            float ss = c[i][0]*c[i][0] + c[i][1]*c[i][1]
                     + c[i][2]*c[i][2] + c[i][3]*c[i][3];
            #pragma unroll
            for (int o = 16; o; o >>= 1)
                ss += __shfl_xor_sync(0xffffffffu, ss, o);
            float s = rsqrtf(ss * (1.0f / CDIM) + 1e-5f);
            float o0 = c[i][0]*s*lw[0], o1 = c[i][1]*s*lw[1];
            float o2 = c[i][2]*s*lw[2], o3 = c[i][3]*s*lw[3];
            size_t off = (size_t)(rowBase + ty*8 + i) * CDIM + tx*4;
            if (midx == 0) {
                float4 ov = {o0, o1, o2, o3};
                *(float4*)(g_q + off) = ov;
            } else {
                __half2 h0 = __floats2half2_rn(o0, o1);
                __half2 h1 = __floats2half2_rn(o2, o3);
                uint2 u; u.x = *(unsigned*)&h0; u.y = *(unsigned*)&h1;
                *(uint2*)(g_kh + off) = u;
            }
        }
    } else if (midx == 2) {
        #pragma unroll
        for (int i = 0; i < 8; i++) {
            __half2 h0 = __floats2half2_rn(c[i][0], c[i][1]);
            __half2 h1 = __floats2half2_rn(c[i][2], c[i][3]);
            uint2 u; u.x = *(unsigned*)&h0; u.y = *(unsigned*)&h1;
            *(uint2*)(g_vh + (size_t)(rowBase + ty*8 + i) * CDIM + tx*4) = u;
        }
    } else {
        #pragma unroll
        for (int i = 0; i < 8; i++) {
            float4 ov;
            ov.x = 1.0f / (1.0f + __expf(-c[i][0]));
            ov.y = 1.0f / (1.0f + __expf(-c[i][1]));
            ov.z = 1.0f / (1.0f + __expf(-c[i][2]));
            ov.w = 1.0f / (1.0f + __expf(-c[i][3]));
            *(float4*)(g_g + (size_t)(rowBase + ty*8 + i) * CDIM + tx*4) = ov;
        }
    }
}

// ============================================================
// K2: attention. One block (256 thr) per query row l.
// ============================================================
__global__ void __launch_bounds__(256) attn_kernel(
    const float* __restrict__ P, const int* __restrict__ idxg,
    const float* __restrict__ Wb)
{
    __shared__ int   idx_s[KNN];
    __shared__ float q_s[CDIM];
    __shared__ float wb_s[NH*CP];
    __shared__ float bias_s[NH][KNN];
    __shared__ float sc[NH][KNN];
    __shared__ float av_red[4][CDIM];

    const int l = blockIdx.x;
    const int t = threadIdx.x;
    const int w = t >> 5, lane = t & 31;

    if (t < KNN) {
        idx_s[t] = idxg[(size_t)l * KNN + t];
        q_s[t]   = g_q[(size_t)l * CDIM + t] * 0.17677669529663687f;
    }
    if (t < NH*CP) wb_s[t] = Wb[t];
    __syncthreads();

    // ---- issue P loads (DRAM) first ----
    int jP  = (w << 4) + (lane >> 1);
    int pp = lane & 1;
    const float* pr = P + ((size_t)l * LQ + idx_s[jP]) * CP + pp * 8;
    float4 p0 = ((const float4*)pr)[0];
    float4 p1 = ((const float4*)pr)[1];

    // ---- scores (fp16 K), 2 batches of 8 preloaded rows ----
    {
        const int head = lane >> 3;
        float4 qf = *(const float4*)&q_s[lane * 4];
        #pragma unroll
        for (int b = 0; b < 2; b++) {
            uint2 kb[8];
            #pragma unroll
            for (int i = 0; i < 8; i++) {
                int j = (w << 4) + b * 8 + i;
                kb[i] = ((const uint2*)(g_kh + (size_t)idx_s[j] * CDIM))[lane];
            }
            #pragma unroll
            for (int i = 0; i < 8; i++) {
                int j = (w << 4) + b * 8 + i;
                float2 k0 = __half22float2(*(__half2*)&kb[i].x);
                float2 k1 = __half22float2(*(__half2*)&kb[i].y);
                float d = qf.x*k0.x + qf.y*k0.y + qf.z*k1.x + qf.w*k1.y;
                d += __shfl_down_sync(0xffffffffu, d, 4, 8);
                d += __shfl_down_sync(0xffffffffu, d, 2, 8);
                d += __shfl_down_sync(0xffffffffu, d, 1, 8);
                if ((lane & 7) == 0) sc[head][j] = d;
            }
        }
    }

    // ---- pair bias from preloaded P ----
    {
        float pv[8] = {p0.x,p0.y,p0.z,p0.w, p1.x,p1.y,p1.z,p1.w};
        float b[NH];
        #pragma unroll
        for (int h = 0; h < NH; h++) {
            const float* wbp = &wb_s[h*CP + pp*8];
            b[h] = pv[0]*wbp[0] + pv[1]*wbp[1] + pv[2]*wbp[2] + pv[3]*wbp[3]
                 + pv[4]*wbp[4] + pv[5]*wbp[5] + pv[6]*wbp[6] + pv[7]*wbp[7];
        }
        #pragma unroll
        for (int h = 0; h < NH; h++) {
            b[h] += __shfl_xor_sync(0xffffffffu, b[h], 1);
            if (pp == 0) bias_s[h][jP] = b[h];
        }
    }
    __syncthreads();

    // ---- softmax per head (warps 0..3) ----
    if (t < 128) {
        int h = w;
        float s0 = sc[h][lane]    + bias_s[h][lane];
        float s1 = sc[h][lane+32] + bias_s[h][lane+32];
        float s2 = sc[h][lane+64] + bias_s[h][lane+64];
        float s3 = sc[h][lane+96] + bias_s[h][lane+96];
        float mx = fmaxf(fmaxf(s0, s1), fmaxf(s2, s3));
        #pragma unroll
        for (int o = 16; o; o >>= 1) mx = fmaxf(mx, __shfl_xor_sync(0xffffffffu, mx, o));
        float e0 = __expf(s0 - mx), e1 = __expf(s1 - mx),
              e2 = __expf(s2 - mx), e3 = __expf(s3 - mx);
        float sum = e0 + e1 + e2 + e3;
        #pragma unroll
        for (int o = 16; o; o >>= 1) sum += __shfl_xor_sync(0xffffffffu, sum, o);
        float inv = 1.0f / sum;
        sc[h][lane]    = e0 * inv;
        sc[h][lane+32] = e1 * inv;
        sc[h][lane+64] = e2 * inv;
        sc[h][lane+96] = e3 * inv;
    }
    __syncthreads();

    // ---- AV (fp16 V), 4 batches of 8 preloaded rows ----
    {
        const int d2 = t & 63;
        const int jg = t >> 6;
        const int h  = d2 >> 4;
        float ax = 0.f, ay = 0.f;
        const unsigned* vbase = (const unsigned*)g_vh;
        #pragma unroll
        for (int b = 0; b < 4; b++) {
            unsigned vb[8];
            #pragma unroll
            for (int i = 0; i < 8; i++) {
                int j = jg * 32 + b * 8 + i;
                vb[i] = vbase[(size_t)idx_s[j] * (CDIM/2) + d2];
            }
            #pragma unroll
            for (int i = 0; i < 8; i++) {
                int j = jg * 32 + b * 8 + i;
                float2 vf = __half22float2(*(__half2*)&vb[i]);
                float p = sc[h][j];
                ax += p * vf.x;
                ay += p * vf.y;
            }
        }
        av_red[jg][2*d2]   = ax;
        av_red[jg][2*d2+1] = ay;
    }
    __syncthreads();
    if (t < CDIM) {
        float o = (av_red[0][t] + av_red[1][t] + av_red[2][t] + av_red[3][t])
                  * g_g[(size_t)l * CDIM + t];
        g_ao[(size_t)l * CDIM + t] = o;
    }
}

// ============================================================
// K3: out = g_ao @ Wo^T  (32-row tiles, grid 128)
// dyn smem: Ast[128*32] + Bst[128*132]
// ============================================================
__global__ void __launch_bounds__(256) out_gemm_kernel(
    const float* __restrict__ Wo, float* __restrict__ out)
{
    extern __shared__ __align__(16) float sm[];
    float* Ast = sm;                  // 128*32
    float* Bst = sm + 128*32;         // 128*132

    const int rowBase = blockIdx.x * 32;
    const int tid = threadIdx.x;

    {
        int r   = tid & 31;
        int seg = tid >> 5;           // 16-float segment
        const float* xp = g_ao + (size_t)(rowBase + r) * CDIM + seg * 16;
        #pragma unroll
        for (int f = 0; f < 4; f++) {
            float4 x = ((const float4*)xp)[f];
            int k = seg * 16 + f * 4;
            Ast[(k+0)*32 + r] = x.x;
            Ast[(k+1)*32 + r] = x.y;
            Ast[(k+2)*32 + r] = x.z;
            Ast[(k+3)*32 + r] = x.w;
        }
        stage_B(Wo, Bst);
    }
    __syncthreads();

    float c[4][4];
    gemm_main<32, 2>(Ast, Bst, c);

    const int tx = tid & 31, ty = tid >> 5;
    #pragma unroll
    for (int i = 0; i < 4; i++) {
        float4 ov = {c[i][0], c[i][1], c[i][2], c[i][3]};
        *(float4*)(out + (size_t)(rowBase + ty*4 + i) * CDIM + tx*4) = ov;
    }
}

// ============================================================
extern "C" void kernel_launch(void* const* d_in, const int* in_sizes, int n_in,
                              void* d_out, int out_size)
{
    const float* Q_L  = (const float*)d_in[0];
    const float* P    = (const float*)d_in[1];
    const int*   idx  = (const int*)  d_in[2];
    const float* Wq   = (const float*)d_in[3];
    const float* Wk   = (const float*)d_in[4];
    const float* Wv   = (const float*)d_in[5];
    const float* Wg   = (const float*)d_in[6];
    const float* Wb   = (const float*)d_in[7];
    const float* Wo   = (const float*)d_in[8];
    const float* ln1  = (const float*)d_in[9];
    const float* lnq  = (const float*)d_in[10];
    const float* lnk  = (const float*)d_in[11];
    float* out = (float*)d_out;

    const int smem_qkvg = (128*64 + 128*BSTRIDE) * sizeof(float);
    const int smem_out  = (128*32 + 128*BSTRIDE) * sizeof(float);
    cudaFuncSetAttribute(qkvg_kernel,
        cudaFuncAttributeMaxDynamicSharedMemorySize, smem_qkvg);
    cudaFuncSetAttribute(out_gemm_kernel,
        cudaFuncAttributeMaxDynamicSharedMemorySize, smem_out);

    dim3 g1(LQ/64, 4);
    qkvg_kernel<<<g1, 256, smem_qkvg>>>(Q_L, Wq, Wk, Wv, Wg, ln1, lnq, lnk);
    attn_kernel<<<LQ, 256>>>(P, idx, Wb);
    out_gemm_kernel<<<LQ/32, 256, smem_out>>>(Wo, out);
}

// round 5
// speedup vs baseline: 1.5136x; 1.0329x over previous
#include <cuda_runtime.h>
#include <cuda_fp16.h>
#include <math.h>
#include <stdint.h>

#define LQ   4096
#define CDIM 128
#define KNN  128
#define NH   4
#define DH   32
#define CP   16

__device__ float  g_q [LQ*CDIM];
__device__ __half g_kh[LQ*CDIM];
__device__ __half g_vh[LQ*CDIM];
__device__ float  g_g [LQ*CDIM];
__device__ float  g_ao[LQ*CDIM];

typedef unsigned long long ull;

#define PACK2(dst, lo, hi) \
    asm("mov.b64 %0, {%1,%2};" : "=l"(dst) : "f"(lo), "f"(hi))
#define UNPACK2(lo, hi, src) \
    asm("mov.b64 {%0,%1}, %2;" : "=f"(lo), "=f"(hi) : "l"(src))
#define FMA2(acc, a, b) \
    asm("fma.rn.f32x2 %0, %1, %2, %0;" : "+l"(acc) : "l"(a), "l"(b))

#define BSTRIDE 132

// ------------------------------------------------------------
// Stage full W [128][128] row-major -> Bst[k][n] (k-major).
// ------------------------------------------------------------
__device__ __forceinline__ void stage_B(const float* __restrict__ W, float* Bst)
{
    const int tid = threadIdx.x;
    const int nW = tid >> 1;
    const int qq = tid & 1;
    #pragma unroll
    for (int kc = 0; kc < CDIM; kc += 16) {
        const float* wp = W + (size_t)nW * CDIM + kc + qq * 8;
        float4 b0 = ((const float4*)wp)[0];
        float4 b1 = ((const float4*)wp)[1];
        int kb = kc + qq * 8;
        Bst[(kb+0)*BSTRIDE + nW] = b0.x;
        Bst[(kb+1)*BSTRIDE + nW] = b0.y;
        Bst[(kb+2)*BSTRIDE + nW] = b0.z;
        Bst[(kb+3)*BSTRIDE + nW] = b0.w;
        Bst[(kb+4)*BSTRIDE + nW] = b1.x;
        Bst[(kb+5)*BSTRIDE + nW] = b1.y;
        Bst[(kb+6)*BSTRIDE + nW] = b1.z;
        Bst[(kb+7)*BSTRIDE + nW] = b1.w;
    }
}

// ------------------------------------------------------------
// Software-pipelined barrier-free mainloop.
// C[ROWS x 128]; NP row-pairs per thread; Ast k-major stride ROWS.
// ------------------------------------------------------------
template<int ROWS, int NP>
__device__ __forceinline__ void gemm_main(
    const float* Ast, const float* Bst, float c[2*NP][4])
{
    const int tid = threadIdx.x;
    const int tx = tid & 31, ty = tid >> 5;
    const float* ap = Ast + ty * (2*NP);
    const float* bp = Bst + tx * 4;

    ull acc[NP][4];
    #pragma unroll
    for (int p = 0; p < NP; p++)
        #pragma unroll
        for (int j = 0; j < 4; j++) acc[p][j] = 0ull;

    ull a0[NP], a1[NP];
    float4 b0, b1;

    // preload kk = 0
    b0 = *(const float4*)bp;
    #pragma unroll
    for (int p = 0; p < NP; p++) a0[p] = ((const ull*)ap)[p];

    #pragma unroll 4
    for (int kk = 0; kk < CDIM - 2; kk += 2) {
        // preload kk+1
        b1 = *(const float4*)(bp + (kk+1) * BSTRIDE);
        #pragma unroll
        for (int p = 0; p < NP; p++)
            a1[p] = ((const ull*)(ap + (kk+1) * ROWS))[p];
        // compute kk
        {
            ull bb0, bb1, bb2, bb3;
            PACK2(bb0, b0.x, b0.x); PACK2(bb1, b0.y, b0.y);
            PACK2(bb2, b0.z, b0.z); PACK2(bb3, b0.w, b0.w);
            #pragma unroll
            for (int p = 0; p < NP; p++) {
                FMA2(acc[p][0], a0[p], bb0);
                FMA2(acc[p][1], a0[p], bb1);
                FMA2(acc[p][2], a0[p], bb2);
                FMA2(acc[p][3], a0[p], bb3);
            }
        }
        // preload kk+2
        b0 = *(const float4*)(bp + (kk+2) * BSTRIDE);
        #pragma unroll
        for (int p = 0; p < NP; p++)
            a0[p] = ((const ull*)(ap + (kk+2) * ROWS))[p];
        // compute kk+1
        {
            ull bb0, bb1, bb2, bb3;
            PACK2(bb0, b1.x, b1.x); PACK2(bb1, b1.y, b1.y);
            PACK2(bb2, b1.z, b1.z); PACK2(bb3, b1.w, b1.w);
            #pragma unroll
            for (int p = 0; p < NP; p++) {
                FMA2(acc[p][0], a1[p], bb0);
                FMA2(acc[p][1], a1[p], bb1);
                FMA2(acc[p][2], a1[p], bb2);
                FMA2(acc[p][3], a1[p], bb3);
            }
        }
    }
    // tail: kk = 126, 127
    b1 = *(const float4*)(bp + 127 * BSTRIDE);
    #pragma unroll
    for (int p = 0; p < NP; p++)
        a1[p] = ((const ull*)(ap + 127 * ROWS))[p];
    {
        ull bb0, bb1, bb2, bb3;
        PACK2(bb0, b0.x, b0.x); PACK2(bb1, b0.y, b0.y);
        PACK2(bb2, b0.z, b0.z); PACK2(bb3, b0.w, b0.w);
        #pragma unroll
        for (int p = 0; p < NP; p++) {
            FMA2(acc[p][0], a0[p], bb0);
            FMA2(acc[p][1], a0[p], bb1);
            FMA2(acc[p][2], a0[p], bb2);
            FMA2(acc[p][3], a0[p], bb3);
        }
    }
    {
        ull bb0, bb1, bb2, bb3;
        PACK2(bb0, b1.x, b1.x); PACK2(bb1, b1.y, b1.y);
        PACK2(bb2, b1.z, b1.z); PACK2(bb3, b1.w, b1.w);
        #pragma unroll
        for (int p = 0; p < NP; p++) {
            FMA2(acc[p][0], a1[p], bb0);
            FMA2(acc[p][1], a1[p], bb1);
            FMA2(acc[p][2], a1[p], bb2);
            FMA2(acc[p][3], a1[p], bb3);
        }
    }

    #pragma unroll
    for (int p = 0; p < NP; p++)
        #pragma unroll
        for (int j = 0; j < 4; j++)
            UNPACK2(c[2*p][j], c[2*p+1][j], acc[p][j]);
}

// ============================================================
// K1: fused rms(Q_L) + {q,k,v,g} projection + epilogues.
// ============================================================
__global__ void __launch_bounds__(256, 2) qkvg_kernel(
    const float* __restrict__ Q_L,
    const float* __restrict__ Wq, const float* __restrict__ Wk,
    const float* __restrict__ Wv, const float* __restrict__ Wg,
    const float* __restrict__ ln1,
    const float* __restrict__ lnq, const float* __restrict__ lnk)
{
    extern __shared__ __align__(16) float sm[];
    float* Ast = sm;                  // 128*64
    float* Bst = sm + 128*64;         // 128*132
    __shared__ float red[64][4];

    const int midx = blockIdx.y;
    const float* W = (midx == 0) ? Wq : (midx == 1) ? Wk : (midx == 2) ? Wv : Wg;
    const int rowBase = blockIdx.x * 64;
    const int tid = threadIdx.x;

    {
        int r    = tid & 63;
        int half = tid >> 6;
        const float* xp = Q_L + (size_t)(rowBase + r) * CDIM + half * 32;
        float4 x[8];
        #pragma unroll
        for (int f = 0; f < 8; f++) x[f] = ((const float4*)xp)[f];
        float ss = 0.f;
        #pragma unroll
        for (int f = 0; f < 8; f++)
            ss += x[f].x*x[f].x + x[f].y*x[f].y + x[f].z*x[f].z + x[f].w*x[f].w;
        red[r][half] = ss;
        stage_B(W, Bst);
        __syncthreads();
        float sa = red[r][0] + red[r][1] + red[r][2] + red[r][3];
        float s = rsqrtf(sa * (1.0f / CDIM) + 1e-5f);
        #pragma unroll
        for (int f = 0; f < 8; f++) {
            int k = half * 32 + f * 4;
            Ast[(k+0)*64 + r] = x[f].x * s * __ldg(ln1 + k + 0);
            Ast[(k+1)*64 + r] = x[f].y * s * __ldg(ln1 + k + 1);
            Ast[(k+2)*64 + r] = x[f].z * s * __ldg(ln1 + k + 2);
            Ast[(k+3)*64 + r] = x[f].w * s * __ldg(ln1 + k + 3);
        }
    }
    __syncthreads();

    float c[8][4];
    gemm_main<64, 4>(Ast, Bst, c);

    const int tx = tid & 31, ty = tid >> 5;

    if (midx < 2) {
        const float* lnw = (midx == 0) ? lnq : lnk;
        float lw[4];
        #pragma unroll
        for (int j = 0; j < 4; j++) lw[j] = lnw[tx * 4 + j];
        #pragma unroll
        for (int i = 0; i < 8; i++) {
            float ss = c[i][0]*c[i][0] + c[i][1]*c[i][1]
                     + c[i][2]*c[i][2] + c[i][3]*c[i][3];
            #pragma unroll
            for (int o = 16; o; o >>= 1)
                ss += __shfl_xor_sync(0xffffffffu, ss, o);
            float s = rsqrtf(ss * (1.0f / CDIM) + 1e-5f);
            float o0 = c[i][0]*s*lw[0], o1 = c[i][1]*s*lw[1];
            float o2 = c[i][2]*s*lw[2], o3 = c[i][3]*s*lw[3];
            size_t off = (size_t)(rowBase + ty*8 + i) * CDIM + tx*4;
            if (midx == 0) {
                float4 ov = {o0, o1, o2, o3};
                *(float4*)(g_q + off) = ov;
            } else {
                __half2 h0 = __floats2half2_rn(o0, o1);
                __half2 h1 = __floats2half2_rn(o2, o3);
                uint2 u; u.x = *(unsigned*)&h0; u.y = *(unsigned*)&h1;
                *(uint2*)(g_kh + off) = u;
            }
        }
    } else if (midx == 2) {
        #pragma unroll
        for (int i = 0; i < 8; i++) {
            __half2 h0 = __floats2half2_rn(c[i][0], c[i][1]);
            __half2 h1 = __floats2half2_rn(c[i][2], c[i][3]);
            uint2 u; u.x = *(unsigned*)&h0; u.y = *(unsigned*)&h1;
            *(uint2*)(g_vh + (size_t)(rowBase + ty*8 + i) * CDIM + tx*4) = u;
        }
    } else {
        #pragma unroll
        for (int i = 0; i < 8; i++) {
            float4 ov;
            ov.x = 1.0f / (1.0f + __expf(-c[i][0]));
            ov.y = 1.0f / (1.0f + __expf(-c[i][1]));
            ov.z = 1.0f / (1.0f + __expf(-c[i][2]));
            ov.w = 1.0f / (1.0f + __expf(-c[i][3]));
            *(float4*)(g_g + (size_t)(rowBase + ty*8 + i) * CDIM + tx*4) = ov;
        }
    }
}

// ============================================================
// K2: attention. One block (256 thr) per query row l.
// ============================================================
__global__ void __launch_bounds__(256) attn_kernel(
    const float* __restrict__ P, const int* __restrict__ idxg,
    const float* __restrict__ Wb)
{
    __shared__ int   idx_s[KNN];
    __shared__ float q_s[CDIM];
    __shared__ float wb_s[NH*CP];
    __shared__ float bias_s[NH][KNN];
    __shared__ float sc[NH][KNN];
    __shared__ float av_red[4][CDIM];

    const int l = blockIdx.x;
    const int t = threadIdx.x;
    const int w = t >> 5, lane = t & 31;

    if (t < KNN) {
        idx_s[t] = idxg[(size_t)l * KNN + t];
        q_s[t]   = g_q[(size_t)l * CDIM + t] * 0.17677669529663687f;
    }
    if (t < NH*CP) wb_s[t] = Wb[t];
    __syncthreads();

    // issue P loads (DRAM) first
    int jP = (w << 4) + (lane >> 1);
    int pp = lane & 1;
    const float* pr = P + ((size_t)l * LQ + idx_s[jP]) * CP + pp * 8;
    float4 p0 = ((const float4*)pr)[0];
    float4 p1 = ((const float4*)pr)[1];

    // scores (fp16 K), batches of 8 preloaded rows
    {
        const int head = lane >> 3;
        float4 qf = *(const float4*)&q_s[lane * 4];
        #pragma unroll
        for (int b = 0; b < 2; b++) {
            uint2 kb[8];
            #pragma unroll
            for (int i = 0; i < 8; i++) {
                int j = (w << 4) + b * 8 + i;
                kb[i] = ((const uint2*)(g_kh + (size_t)idx_s[j] * CDIM))[lane];
            }
            #pragma unroll
            for (int i = 0; i < 8; i++) {
                int j = (w << 4) + b * 8 + i;
                float2 k0 = __half22float2(*(__half2*)&kb[i].x);
                float2 k1 = __half22float2(*(__half2*)&kb[i].y);
                float d = qf.x*k0.x + qf.y*k0.y + qf.z*k1.x + qf.w*k1.y;
                d += __shfl_down_sync(0xffffffffu, d, 4, 8);
                d += __shfl_down_sync(0xffffffffu, d, 2, 8);
                d += __shfl_down_sync(0xffffffffu, d, 1, 8);
                if ((lane & 7) == 0) sc[head][j] = d;
            }
        }
    }

    // pair bias from preloaded P
    {
        float pv[8] = {p0.x,p0.y,p0.z,p0.w, p1.x,p1.y,p1.z,p1.w};
        float b[NH];
        #pragma unroll
        for (int h = 0; h < NH; h++) {
            const float* wbp = &wb_s[h*CP + pp*8];
            b[h] = pv[0]*wbp[0] + pv[1]*wbp[1] + pv[2]*wbp[2] + pv[3]*wbp[3]
                 + pv[4]*wbp[4] + pv[5]*wbp[5] + pv[6]*wbp[6] + pv[7]*wbp[7];
        }
        #pragma unroll
        for (int h = 0; h < NH; h++) {
            b[h] += __shfl_xor_sync(0xffffffffu, b[h], 1);
            if (pp == 0) bias_s[h][jP] = b[h];
        }
    }
    __syncthreads();

    // softmax per head (warps 0..3)
    if (t < 128) {
        int h = w;
        float s0 = sc[h][lane]    + bias_s[h][lane];
        float s1 = sc[h][lane+32] + bias_s[h][lane+32];
        float s2 = sc[h][lane+64] + bias_s[h][lane+64];
        float s3 = sc[h][lane+96] + bias_s[h][lane+96];
        float mx = fmaxf(fmaxf(s0, s1), fmaxf(s2, s3));
        #pragma unroll
        for (int o = 16; o; o >>= 1) mx = fmaxf(mx, __shfl_xor_sync(0xffffffffu, mx, o));
        float e0 = __expf(s0 - mx), e1 = __expf(s1 - mx),
              e2 = __expf(s2 - mx), e3 = __expf(s3 - mx);
        float sum = e0 + e1 + e2 + e3;
        #pragma unroll
        for (int o = 16; o; o >>= 1) sum += __shfl_xor_sync(0xffffffffu, sum, o);
        float inv = 1.0f / sum;
        sc[h][lane]    = e0 * inv;
        sc[h][lane+32] = e1 * inv;
        sc[h][lane+64] = e2 * inv;
        sc[h][lane+96] = e3 * inv;
    }
    __syncthreads();

    // AV (fp16 V)
    {
        const int d2 = t & 63;
        const int jg = t >> 6;
        const int h  = d2 >> 4;
        float ax = 0.f, ay = 0.f;
        const unsigned* vbase = (const unsigned*)g_vh;
        #pragma unroll
        for (int b = 0; b < 4; b++) {
            unsigned vb[8];
            #pragma unroll
            for (int i = 0; i < 8; i++) {
                int j = jg * 32 + b * 8 + i;
                vb[i] = vbase[(size_t)idx_s[j] * (CDIM/2) + d2];
            }
            #pragma unroll
            for (int i = 0; i < 8; i++) {
                int j = jg * 32 + b * 8 + i;
                float2 vf = __half22float2(*(__half2*)&vb[i]);
                float p = sc[h][j];
                ax += p * vf.x;
                ay += p * vf.y;
            }
        }
        av_red[jg][2*d2]   = ax;
        av_red[jg][2*d2+1] = ay;
    }
    __syncthreads();
    if (t < CDIM) {
        float o = (av_red[0][t] + av_red[1][t] + av_red[2][t] + av_red[3][t])
                  * g_g[(size_t)l * CDIM + t];
        g_ao[(size_t)l * CDIM + t] = o;
    }
}

// ============================================================
// K3: out = g_ao @ Wo^T  (32-row tiles, grid 128)
// ============================================================
__global__ void __launch_bounds__(256, 2) out_gemm_kernel(
    const float* __restrict__ Wo, float* __restrict__ out)
{
    extern __shared__ __align__(16) float sm[];
    float* Ast = sm;                  // 128*32
    float* Bst = sm + 128*32;         // 128*132

    const int rowBase = blockIdx.x * 32;
    const int tid = threadIdx.x;

    {
        int r   = tid & 31;
        int seg = tid >> 5;
        const float* xp = g_ao + (size_t)(rowBase + r) * CDIM + seg * 16;
        #pragma unroll
        for (int f = 0; f < 4; f++) {
            float4 x = ((const float4*)xp)[f];
            int k = seg * 16 + f * 4;
            Ast[(k+0)*32 + r] = x.x;
            Ast[(k+1)*32 + r] = x.y;
            Ast[(k+2)*32 + r] = x.z;
            Ast[(k+3)*32 + r] = x.w;
        }
        stage_B(Wo, Bst);
    }
    __syncthreads();

    float c[4][4];
    gemm_main<32, 2>(Ast, Bst, c);

    const int tx = tid & 31, ty = tid >> 5;
    #pragma unroll
    for (int i = 0; i < 4; i++) {
        float4 ov = {c[i][0], c[i][1], c[i][2], c[i][3]};
        *(float4*)(out + (size_t)(rowBase + ty*4 + i) * CDIM + tx*4) = ov;
    }
}

// ============================================================
extern "C" void kernel_launch(void* const* d_in, const int* in_sizes, int n_in,
                              void* d_out, int out_size)
{
    const float* Q_L  = (const float*)d_in[0];
    const float* P    = (const float*)d_in[1];
    const int*   idx  = (const int*)  d_in[2];
    const float* Wq   = (const float*)d_in[3];
    const float* Wk   = (const float*)d_in[4];
    const float* Wv   = (const float*)d_in[5];
    const float* Wg   = (const float*)d_in[6];
    const float* Wb   = (const float*)d_in[7];
    const float* Wo   = (const float*)d_in[8];
    const float* ln1  = (const float*)d_in[9];
    const float* lnq  = (const float*)d_in[10];
    const float* lnk  = (const float*)d_in[11];
    float* out = (float*)d_out;

    const int smem_qkvg = (128*64 + 128*BSTRIDE) * sizeof(float);
    const int smem_out  = (128*32 + 128*BSTRIDE) * sizeof(float);
    cudaFuncSetAttribute(qkvg_kernel,
        cudaFuncAttributeMaxDynamicSharedMemorySize, smem_qkvg);
    cudaFuncSetAttribute(out_gemm_kernel,
        cudaFuncAttributeMaxDynamicSharedMemorySize, smem_out);

    dim3 g1(LQ/64, 4);
    qkvg_kernel<<<g1, 256, smem_qkvg>>>(Q_L, Wq, Wk, Wv, Wg, ln1, lnq, lnk);
    attn_kernel<<<LQ, 256>>>(P, idx, Wb);
    out_gemm_kernel<<<LQ/32, 256, smem_out>>>(Wo, out);
}

// round 7
// speedup vs baseline: 1.6661x; 1.1008x over previous
#include <cuda_runtime.h>
#include <cuda_fp16.h>
#include <math.h>
#include <stdint.h>

#define LQ   4096
#define CDIM 128
#define KNN  128
#define NH   4
#define DH   32
#define CP   16

__device__ float  g_q [LQ*CDIM];
__device__ __half g_kh[LQ*CDIM];
__device__ __half g_vh[LQ*CDIM];
__device__ float  g_g [LQ*CDIM];
__device__ float  g_ao[LQ*CDIM];

typedef unsigned long long ull;

#define PACK2(dst, lo, hi) \
    asm("mov.b64 %0, {%1,%2};" : "=l"(dst) : "f"(lo), "f"(hi))
#define UNPACK2(lo, hi, src) \
    asm("mov.b64 {%0,%1}, %2;" : "=f"(lo), "=f"(hi) : "l"(src))
#define FMA2(acc, a, b) \
    asm("fma.rn.f32x2 %0, %1, %2, %0;" : "+l"(acc) : "l"(a), "l"(b))

#define BSTRIDE 132
#define HSTRIDE 136          // fp16 tile row stride (halves)
#define DSTRIDE 132          // D scratch row stride (floats)

__device__ __forceinline__ uint32_t smem_u32(const void* p) {
    uint32_t a;
    asm("{ .reg .u64 t; cvta.to.shared.u64 t, %1; cvt.u32.u64 %0, t; }"
        : "=r"(a) : "l"(p));
    return a;
}

#define LDMATRIX_X4(r0, r1, r2, r3, addr) \
    asm volatile("ldmatrix.sync.aligned.m8n8.x4.shared.b16 {%0,%1,%2,%3}, [%4];" \
                 : "=r"(r0), "=r"(r1), "=r"(r2), "=r"(r3) : "r"(addr))

#define MMA16816(d, a, b) \
    asm volatile("mma.sync.aligned.m16n8k16.row.col.f32.f16.f16.f32 " \
                 "{%0,%1,%2,%3}, {%4,%5,%6,%7}, {%8,%9}, {%0,%1,%2,%3};" \
                 : "+f"((d)[0]), "+f"((d)[1]), "+f"((d)[2]), "+f"((d)[3]) \
                 : "r"((a)[0]), "r"((a)[1]), "r"((a)[2]), "r"((a)[3]), \
                   "r"((b)[0]), "r"((b)[1]))

// ============================================================
// K1 (HMMA): fused rms(Q_L) + {q,k,v,g} projection + epilogues.
// grid (32 row-tiles, 4 matrices), 256 threads (8 warps).
// C[128x128] = A[128x128] @ W^T, fp16 in / fp32 accum.
// ============================================================
__global__ void __launch_bounds__(256) qkvg_mma_kernel(
    const float* __restrict__ Q_L,
    const float* __restrict__ Wq, const float* __restrict__ Wk,
    const float* __restrict__ Wv, const float* __restrict__ Wg,
    const float* __restrict__ ln1,
    const float* __restrict__ lnq, const float* __restrict__ lnk)
{
    extern __shared__ __align__(16) char smc[];
    __half* Ah = (__half*)smc;                         // [128][136]
    __half* Bh = (__half*)(smc + 128*HSTRIDE*2);       // [128][136]
    float*  Dsm = (float*)smc;                         // reuse: [128][132]
    __shared__ float ln1_s[CDIM];
    __shared__ float lnw_s[CDIM];

    const int midx = blockIdx.y;
    const float* W = (midx == 0) ? Wq : (midx == 1) ? Wk : (midx == 2) ? Wv : Wg;
    const int rowBase = blockIdx.x * 128;
    const int tid  = threadIdx.x;
    const int wid  = tid >> 5, lane = tid & 31;

    if (tid < CDIM) {
        ln1_s[tid] = ln1[tid];
        lnw_s[tid] = (midx == 0) ? lnq[tid] : (midx == 1) ? lnk[tid] : 0.f;
    }
    __syncthreads();

    // ---- stage A (rms'd, fp16) and B (W, fp16); half row per thread ----
    {
        const int r = tid >> 1, h = tid & 1;
        const float4* xp = (const float4*)(Q_L + (size_t)(rowBase + r) * CDIM + h * 64);
        float4 xv[16];
        float ss = 0.f;
        #pragma unroll
        for (int i = 0; i < 16; i++) {
            xv[i] = xp[i];
            ss += xv[i].x*xv[i].x + xv[i].y*xv[i].y
                + xv[i].z*xv[i].z + xv[i].w*xv[i].w;
        }
        ss += __shfl_xor_sync(0xffffffffu, ss, 1);
        float s = rsqrtf(ss * (1.0f / CDIM) + 1e-5f);
        __half* ar = Ah + r * HSTRIDE + h * 64;
        #pragma unroll
        for (int i = 0; i < 16; i++) {
            int c = h * 64 + i * 4;
            __half2 h0 = __floats2half2_rn(xv[i].x*s*ln1_s[c+0], xv[i].y*s*ln1_s[c+1]);
            __half2 h1 = __floats2half2_rn(xv[i].z*s*ln1_s[c+2], xv[i].w*s*ln1_s[c+3]);
            uint2 u; u.x = *(unsigned*)&h0; u.y = *(unsigned*)&h1;
            *(uint2*)(ar + i * 4) = u;
        }
        const float4* wp = (const float4*)(W + (size_t)r * CDIM + h * 64);
        __half* br = Bh + r * HSTRIDE + h * 64;
        #pragma unroll
        for (int i = 0; i < 16; i++) {
            float4 wv = wp[i];
            __half2 h0 = __floats2half2_rn(wv.x, wv.y);
            __half2 h1 = __floats2half2_rn(wv.z, wv.w);
            uint2 u; u.x = *(unsigned*)&h0; u.y = *(unsigned*)&h1;
            *(uint2*)(br + i * 4) = u;
        }
    }
    __syncthreads();

    // ---- mainloop: warp tile 32(m) x 64(n) ----
    const int wm = (wid & 3) * 32;
    const int wn = (wid >> 2) * 64;
    const uint32_t uA = smem_u32(Ah);
    const uint32_t uB = smem_u32(Bh);

    float d[2][8][4];
    #pragma unroll
    for (int mf = 0; mf < 2; mf++)
        #pragma unroll
        for (int nf = 0; nf < 8; nf++)
            #pragma unroll
            for (int e = 0; e < 4; e++) d[mf][nf][e] = 0.f;

    #pragma unroll
    for (int ks = 0; ks < 8; ks++) {
        const int kk = ks * 16;
        // A fragments (2 m-frags)
        uint32_t a[2][4];
        #pragma unroll
        for (int mf = 0; mf < 2; mf++) {
            int row = wm + mf * 16 + (lane & 15);
            int kc  = kk + ((lane >> 4) << 3);
            uint32_t addr = uA + (uint32_t)(row * HSTRIDE + kc) * 2;
            LDMATRIX_X4(a[mf][0], a[mf][1], a[mf][2], a[mf][3], addr);
        }
        // B fragments (8 n-frags, loaded 2 at a time)
        uint32_t b[8][2];
        #pragma unroll
        for (int np = 0; np < 4; np++) {
            int n0  = wn + np * 16;
            int row = n0 + (lane & 7) + ((lane >> 4) << 3);
            int kc  = kk + ((lane & 8) ? 8 : 0);
            uint32_t addr = uB + (uint32_t)(row * HSTRIDE + kc) * 2;
            uint32_t r0, r1, r2, r3;
            LDMATRIX_X4(r0, r1, r2, r3, addr);
            b[np*2][0]   = r0; b[np*2][1]   = r1;
            b[np*2+1][0] = r2; b[np*2+1][1] = r3;
        }
        #pragma unroll
        for (int mf = 0; mf < 2; mf++)
            #pragma unroll
            for (int nf = 0; nf < 8; nf++)
                MMA16816(d[mf][nf], a[mf], b[nf]);
    }

    // ---- dump D to smem (reuses A/B space) ----
    __syncthreads();
    {
        const int g = lane >> 2, t = lane & 3;
        #pragma unroll
        for (int mf = 0; mf < 2; mf++) {
            #pragma unroll
            for (int nf = 0; nf < 8; nf++) {
                int row = wm + mf * 16 + g;
                int col = wn + nf * 8 + t * 2;
                Dsm[row * DSTRIDE + col]       = d[mf][nf][0];
                Dsm[row * DSTRIDE + col + 1]   = d[mf][nf][1];
                Dsm[(row+8) * DSTRIDE + col]   = d[mf][nf][2];
                Dsm[(row+8) * DSTRIDE + col+1] = d[mf][nf][3];
            }
        }
    }
    __syncthreads();

    // ---- epilogue: half row per thread ----
    {
        const int r = tid >> 1, h = tid & 1;
        const float4* dr = (const float4*)(Dsm + r * DSTRIDE + h * 64);
        const size_t orow = (size_t)(rowBase + r) * CDIM + h * 64;

        if (midx < 2) {
            float ss = 0.f;
            #pragma unroll
            for (int i = 0; i < 16; i++) {
                float4 v = dr[i];
                ss += v.x*v.x + v.y*v.y + v.z*v.z + v.w*v.w;
            }
            ss += __shfl_xor_sync(0xffffffffu, ss, 1);
            float s = rsqrtf(ss * (1.0f / CDIM) + 1e-5f);
            if (midx == 0) {
                #pragma unroll
                for (int i = 0; i < 16; i++) {
                    float4 v = dr[i];
                    int c = h * 64 + i * 4;
                    float4 o = {v.x*s*lnw_s[c+0], v.y*s*lnw_s[c+1],
                                v.z*s*lnw_s[c+2], v.w*s*lnw_s[c+3]};
                    *(float4*)(g_q + orow + i * 4) = o;
                }
            } else {
                #pragma unroll
                for (int i = 0; i < 8; i++) {
                    float4 v0 = dr[i*2], v1 = dr[i*2+1];
                    int c = h * 64 + i * 8;
                    __half2 h0 = __floats2half2_rn(v0.x*s*lnw_s[c+0], v0.y*s*lnw_s[c+1]);
                    __half2 h1 = __floats2half2_rn(v0.z*s*lnw_s[c+2], v0.w*s*lnw_s[c+3]);
                    __half2 h2 = __floats2half2_rn(v1.x*s*lnw_s[c+4], v1.y*s*lnw_s[c+5]);
                    __half2 h3 = __floats2half2_rn(v1.z*s*lnw_s[c+6], v1.w*s*lnw_s[c+7]);
                    uint4 u;
                    u.x = *(unsigned*)&h0; u.y = *(unsigned*)&h1;
                    u.z = *(unsigned*)&h2; u.w = *(unsigned*)&h3;
                    *(uint4*)(g_kh + orow + i * 8) = u;
                }
            }
        } else if (midx == 2) {
            #pragma unroll
            for (int i = 0; i < 8; i++) {
                float4 v0 = dr[i*2], v1 = dr[i*2+1];
                __half2 h0 = __floats2half2_rn(v0.x, v0.y);
                __half2 h1 = __floats2half2_rn(v0.z, v0.w);
                __half2 h2 = __floats2half2_rn(v1.x, v1.y);
                __half2 h3 = __floats2half2_rn(v1.z, v1.w);
                uint4 u;
                u.x = *(unsigned*)&h0; u.y = *(unsigned*)&h1;
                u.z = *(unsigned*)&h2; u.w = *(unsigned*)&h3;
                *(uint4*)(g_vh + orow + i * 8) = u;
            }
        } else {
            #pragma unroll
            for (int i = 0; i < 16; i++) {
                float4 v = dr[i];
                float4 o;
                o.x = 1.0f / (1.0f + __expf(-v.x));
                o.y = 1.0f / (1.0f + __expf(-v.y));
                o.z = 1.0f / (1.0f + __expf(-v.z));
                o.w = 1.0f / (1.0f + __expf(-v.w));
                *(float4*)(g_g + orow + i * 4) = o;
            }
        }
    }
}

// ============================================================
// K2: attention (unchanged). One block (256 thr) per query row.
// ============================================================
__global__ void __launch_bounds__(256) attn_kernel(
    const float* __restrict__ P, const int* __restrict__ idxg,
    const float* __restrict__ Wb)
{
    __shared__ int   idx_s[KNN];
    __shared__ float q_s[CDIM];
    __shared__ float wb_s[NH*CP];
    __shared__ float bias_s[NH][KNN];
    __shared__ float sc[NH][KNN];
    __shared__ float av_red[4][CDIM];

    const int l = blockIdx.x;
    const int t = threadIdx.x;
    const int w = t >> 5, lane = t & 31;

    if (t < KNN) {
        idx_s[t] = idxg[(size_t)l * KNN + t];
        q_s[t]   = g_q[(size_t)l * CDIM + t] * 0.17677669529663687f;
    }
    if (t < NH*CP) wb_s[t] = Wb[t];
    __syncthreads();

    int jP = (w << 4) + (lane >> 1);
    int pp = lane & 1;
    const float* pr = P + ((size_t)l * LQ + idx_s[jP]) * CP + pp * 8;
    float4 p0 = ((const float4*)pr)[0];
    float4 p1 = ((const float4*)pr)[1];

    {
        const int head = lane >> 3;
        float4 qf = *(const float4*)&q_s[lane * 4];
        #pragma unroll
        for (int b = 0; b < 2; b++) {
            uint2 kb[8];
            #pragma unroll
            for (int i = 0; i < 8; i++) {
                int j = (w << 4) + b * 8 + i;
                kb[i] = ((const uint2*)(g_kh + (size_t)idx_s[j] * CDIM))[lane];
            }
            #pragma unroll
            for (int i = 0; i < 8; i++) {
                int j = (w << 4) + b * 8 + i;
                float2 k0 = __half22float2(*(__half2*)&kb[i].x);
                float2 k1 = __half22float2(*(__half2*)&kb[i].y);
                float d = qf.x*k0.x + qf.y*k0.y + qf.z*k1.x + qf.w*k1.y;
                d += __shfl_down_sync(0xffffffffu, d, 4, 8);
                d += __shfl_down_sync(0xffffffffu, d, 2, 8);
                d += __shfl_down_sync(0xffffffffu, d, 1, 8);
                if ((lane & 7) == 0) sc[head][j] = d;
            }
        }
    }

    {
        float pv[8] = {p0.x,p0.y,p0.z,p0.w, p1.x,p1.y,p1.z,p1.w};
        float b[NH];
        #pragma unroll
        for (int h = 0; h < NH; h++) {
            const float* wbp = &wb_s[h*CP + pp*8];
            b[h] = pv[0]*wbp[0] + pv[1]*wbp[1] + pv[2]*wbp[2] + pv[3]*wbp[3]
                 + pv[4]*wbp[4] + pv[5]*wbp[5] + pv[6]*wbp[6] + pv[7]*wbp[7];
        }
        #pragma unroll
        for (int h = 0; h < NH; h++) {
            b[h] += __shfl_xor_sync(0xffffffffu, b[h], 1);
            if (pp == 0) bias_s[h][jP] = b[h];
        }
    }
    __syncthreads();

    if (t < 128) {
        int h = w;
        float s0 = sc[h][lane]    + bias_s[h][lane];
        float s1 = sc[h][lane+32] + bias_s[h][lane+32];
        float s2 = sc[h][lane+64] + bias_s[h][lane+64];
        float s3 = sc[h][lane+96] + bias_s[h][lane+96];
        float mx = fmaxf(fmaxf(s0, s1), fmaxf(s2, s3));
        #pragma unroll
        for (int o = 16; o; o >>= 1) mx = fmaxf(mx, __shfl_xor_sync(0xffffffffu, mx, o));
        float e0 = __expf(s0 - mx), e1 = __expf(s1 - mx),
              e2 = __expf(s2 - mx), e3 = __expf(s3 - mx);
        float sum = e0 + e1 + e2 + e3;
        #pragma unroll
        for (int o = 16; o; o >>= 1) sum += __shfl_xor_sync(0xffffffffu, sum, o);
        float inv = 1.0f / sum;
        sc[h][lane]    = e0 * inv;
        sc[h][lane+32] = e1 * inv;
        sc[h][lane+64] = e2 * inv;
        sc[h][lane+96] = e3 * inv;
    }
    __syncthreads();

    {
        const int d2 = t & 63;
        const int jg = t >> 6;
        const int h  = d2 >> 4;
        float ax = 0.f, ay = 0.f;
        const unsigned* vbase = (const unsigned*)g_vh;
        #pragma unroll
        for (int b = 0; b < 4; b++) {
            unsigned vb[8];
            #pragma unroll
            for (int i = 0; i < 8; i++) {
                int j = jg * 32 + b * 8 + i;
                vb[i] = vbase[(size_t)idx_s[j] * (CDIM/2) + d2];
            }
            #pragma unroll
            for (int i = 0; i < 8; i++) {
                int j = jg * 32 + b * 8 + i;
                float2 vf = __half22float2(*(__half2*)&vb[i]);
                float p = sc[h][j];
                ax += p * vf.x;
                ay += p * vf.y;
            }
        }
        av_red[jg][2*d2]   = ax;
        av_red[jg][2*d2+1] = ay;
    }
    __syncthreads();
    if (t < CDIM) {
        float o = (av_red[0][t] + av_red[1][t] + av_red[2][t] + av_red[3][t])
                  * g_g[(size_t)l * CDIM + t];
        g_ao[(size_t)l * CDIM + t] = o;
    }
}

// ============================================================
// K3: out = g_ao @ Wo^T (FFMA2 path, unchanged)
// ============================================================
__device__ __forceinline__ void stage_B(const float* __restrict__ W, float* Bst)
{
    const int tid = threadIdx.x;
    const int nW = tid >> 1;
    const int qq = tid & 1;
    #pragma unroll
    for (int kc = 0; kc < CDIM; kc += 16) {
        const float* wp = W + (size_t)nW * CDIM + kc + qq * 8;
        float4 b0 = ((const float4*)wp)[0];
        float4 b1 = ((const float4*)wp)[1];
        int kb = kc + qq * 8;
        Bst[(kb+0)*BSTRIDE + nW] = b0.x;
        Bst[(kb+1)*BSTRIDE + nW] = b0.y;
        Bst[(kb+2)*BSTRIDE + nW] = b0.z;
        Bst[(kb+3)*BSTRIDE + nW] = b0.w;
        Bst[(kb+4)*BSTRIDE + nW] = b1.x;
        Bst[(kb+5)*BSTRIDE + nW] = b1.y;
        Bst[(kb+6)*BSTRIDE + nW] = b1.z;
        Bst[(kb+7)*BSTRIDE + nW] = b1.w;
    }
}

template<int ROWS, int NP>
__device__ __forceinline__ void gemm_main(
    const float* Ast, const float* Bst, float c[2*NP][4])
{
    const int tid = threadIdx.x;
    const int tx = tid & 31, ty = tid >> 5;
    const float* ap = Ast + ty * (2*NP);
    const float* bp = Bst + tx * 4;

    ull acc[NP][4];
    #pragma unroll
    for (int p = 0; p < NP; p++)
        #pragma unroll
        for (int j = 0; j < 4; j++) acc[p][j] = 0ull;

    #pragma unroll 8
    for (int kk = 0; kk < CDIM; kk++) {
        const ull* a2 = (const ull*)(ap + kk * ROWS);
        float4 bv = *(const float4*)(bp + kk * BSTRIDE);
        ull bb0, bb1, bb2, bb3;
        PACK2(bb0, bv.x, bv.x); PACK2(bb1, bv.y, bv.y);
        PACK2(bb2, bv.z, bv.z); PACK2(bb3, bv.w, bv.w);
        #pragma unroll
        for (int p = 0; p < NP; p++) {
            ull av = a2[p];
            FMA2(acc[p][0], av, bb0);
            FMA2(acc[p][1], av, bb1);
            FMA2(acc[p][2], av, bb2);
            FMA2(acc[p][3], av, bb3);
        }
    }
    #pragma unroll
    for (int p = 0; p < NP; p++)
        #pragma unroll
        for (int j = 0; j < 4; j++)
            UNPACK2(c[2*p][j], c[2*p+1][j], acc[p][j]);
}

__global__ void __launch_bounds__(256, 2) out_gemm_kernel(
    const float* __restrict__ Wo, float* __restrict__ out)
{
    extern __shared__ __align__(16) float sm[];
    float* Ast = sm;
    float* Bst = sm + 128*32;

    const int rowBase = blockIdx.x * 32;
    const int tid = threadIdx.x;

    {
        int r   = tid & 31;
        int seg = tid >> 5;
        const float* xp = g_ao + (size_t)(rowBase + r) * CDIM + seg * 16;
        #pragma unroll
        for (int f = 0; f < 4; f++) {
            float4 x = ((const float4*)xp)[f];
            int k = seg * 16 + f * 4;
            Ast[(k+0)*32 + r] = x.x;
            Ast[(k+1)*32 + r] = x.y;
            Ast[(k+2)*32 + r] = x.z;
            Ast[(k+3)*32 + r] = x.w;
        }
        stage_B(Wo, Bst);
    }
    __syncthreads();

    float c[4][4];
    gemm_main<32, 2>(Ast, Bst, c);

    const int tx = tid & 31, ty = tid >> 5;
    #pragma unroll
    for (int i = 0; i < 4; i++) {
        float4 ov = {c[i][0], c[i][1], c[i][2], c[i][3]};
        *(float4*)(out + (size_t)(rowBase + ty*4 + i) * CDIM + tx*4) = ov;
    }
}

// ============================================================
extern "C" void kernel_launch(void* const* d_in, const int* in_sizes, int n_in,
                              void* d_out, int out_size)
{
    const float* Q_L  = (const float*)d_in[0];
    const float* P    = (const float*)d_in[1];
    const int*   idx  = (const int*)  d_in[2];
    const float* Wq   = (const float*)d_in[3];
    const float* Wk   = (const float*)d_in[4];
    const float* Wv   = (const float*)d_in[5];
    const float* Wg   = (const float*)d_in[6];
    const float* Wb   = (const float*)d_in[7];
    const float* Wo   = (const float*)d_in[8];
    const float* ln1  = (const float*)d_in[9];
    const float* lnq  = (const float*)d_in[10];
    const float* lnk  = (const float*)d_in[11];
    float* out = (float*)d_out;

    const int smem_qkvg = 2 * 128 * HSTRIDE * 2;   // two fp16 tiles (> D scratch)
    const int smem_out  = (128*32 + 128*BSTRIDE) * sizeof(float);
    cudaFuncSetAttribute(qkvg_mma_kernel,
        cudaFuncAttributeMaxDynamicSharedMemorySize, smem_qkvg);
    cudaFuncSetAttribute(out_gemm_kernel,
        cudaFuncAttributeMaxDynamicSharedMemorySize, smem_out);

    dim3 g1(LQ/128, 4);
    qkvg_mma_kernel<<<g1, 256, smem_qkvg>>>(Q_L, Wq, Wk, Wv, Wg, ln1, lnq, lnk);
    attn_kernel<<<LQ, 256>>>(P, idx, Wb);
    out_gemm_kernel<<<LQ/32, 256, smem_out>>>(Wo, out);
}

// round 8
// speedup vs baseline: 1.6818x; 1.0094x over previous
#include <cuda_runtime.h>
#include <cuda_fp16.h>
#include <math.h>
#include <stdint.h>

#define LQ   4096
#define CDIM 128
#define KNN  128
#define NH   4
#define DH   32
#define CP   16

__device__ float  g_q [LQ*CDIM];
__device__ __half g_kh[LQ*CDIM];
__device__ __half g_vh[LQ*CDIM];
__device__ float  g_g [LQ*CDIM];
__device__ float  g_ao[LQ*CDIM];

#define HSTRIDE 136          // fp16 tile row stride (halves)

__device__ __forceinline__ uint32_t smem_u32(const void* p) {
    uint32_t a;
    asm("{ .reg .u64 t; cvta.to.shared.u64 t, %1; cvt.u32.u64 %0, t; }"
        : "=r"(a) : "l"(p));
    return a;
}

#define LDMATRIX_X4(r0, r1, r2, r3, addr) \
    asm volatile("ldmatrix.sync.aligned.m8n8.x4.shared.b16 {%0,%1,%2,%3}, [%4];" \
                 : "=r"(r0), "=r"(r1), "=r"(r2), "=r"(r3) : "r"(addr))

#define MMA16816(d, a, b) \
    asm volatile("mma.sync.aligned.m16n8k16.row.col.f32.f16.f16.f32 " \
                 "{%0,%1,%2,%3}, {%4,%5,%6,%7}, {%8,%9}, {%0,%1,%2,%3};" \
                 : "+f"((d)[0]), "+f"((d)[1]), "+f"((d)[2]), "+f"((d)[3]) \
                 : "r"((a)[0]), "r"((a)[1]), "r"((a)[2]), "r"((a)[3]), \
                   "r"((b)[0]), "r"((b)[1]))

// ============================================================
// K1 (HMMA): fused rms(Q_L) + {q,k,v,g} projection + epilogues.
// grid (64 row-tiles, 4 matrices), 256 thr. C[64x128] per CTA.
// Register-direct epilogue (no D smem round-trip).
// ============================================================
__global__ void __launch_bounds__(256, 2) qkvg_mma_kernel(
    const float* __restrict__ Q_L,
    const float* __restrict__ Wq, const float* __restrict__ Wk,
    const float* __restrict__ Wv, const float* __restrict__ Wg,
    const float* __restrict__ ln1,
    const float* __restrict__ lnq, const float* __restrict__ lnk)
{
    extern __shared__ __align__(16) char smc[];
    __half* Ah = (__half*)smc;                        // [64][136]
    __half* Bh = (__half*)(smc + 64*HSTRIDE*2);       // [128][136]
    __shared__ float ln1_s[CDIM];
    __shared__ float lnw_s[CDIM];
    __shared__ float ssred[64][5];

    const int midx = blockIdx.y;
    const float* W = (midx == 0) ? Wq : (midx == 1) ? Wk : (midx == 2) ? Wv : Wg;
    const int rowBase = blockIdx.x * 64;
    const int tid  = threadIdx.x;
    const int wid  = tid >> 5, lane = tid & 31;

    if (tid < CDIM) {
        ln1_s[tid] = ln1[tid];
        lnw_s[tid] = (midx == 0) ? lnq[tid] : (midx == 1) ? lnk[tid] : 0.f;
    }
    __syncthreads();

    // ---- stage A (rms'd fp16): 4 thr/row, 32 cols each ----
    {
        const int r = tid >> 2, q4 = tid & 3;
        const float4* xp = (const float4*)(Q_L + (size_t)(rowBase + r) * CDIM + q4 * 32);
        float4 xv[8];
        float ss = 0.f;
        #pragma unroll
        for (int i = 0; i < 8; i++) {
            xv[i] = xp[i];
            ss += xv[i].x*xv[i].x + xv[i].y*xv[i].y
                + xv[i].z*xv[i].z + xv[i].w*xv[i].w;
        }
        ss += __shfl_xor_sync(0xffffffffu, ss, 1);
        ss += __shfl_xor_sync(0xffffffffu, ss, 2);
        float s = rsqrtf(ss * (1.0f / CDIM) + 1e-5f);
        __half* ar = Ah + r * HSTRIDE + q4 * 32;
        #pragma unroll
        for (int i = 0; i < 8; i++) {
            int c = q4 * 32 + i * 4;
            __half2 h0 = __floats2half2_rn(xv[i].x*s*ln1_s[c+0], xv[i].y*s*ln1_s[c+1]);
            __half2 h1 = __floats2half2_rn(xv[i].z*s*ln1_s[c+2], xv[i].w*s*ln1_s[c+3]);
            uint2 u; u.x = *(unsigned*)&h0; u.y = *(unsigned*)&h1;
            *(uint2*)(ar + i * 4) = u;
        }
    }
    // ---- stage B = fp16(W); 2 thr/row, 64 cols each ----
    {
        const int r = tid >> 1, h = tid & 1;
        const float4* wp = (const float4*)(W + (size_t)r * CDIM + h * 64);
        __half* br = Bh + r * HSTRIDE + h * 64;
        #pragma unroll
        for (int i = 0; i < 16; i++) {
            float4 wv = wp[i];
            __half2 h0 = __floats2half2_rn(wv.x, wv.y);
            __half2 h1 = __floats2half2_rn(wv.z, wv.w);
            uint2 u; u.x = *(unsigned*)&h0; u.y = *(unsigned*)&h1;
            *(uint2*)(br + i * 4) = u;
        }
    }
    __syncthreads();

    // ---- mainloop: warp tile 32(m) x 32(n) ----
    const int wm = (wid & 1) * 32;
    const int wn = (wid >> 1) * 32;
    const uint32_t uA = smem_u32(Ah);
    const uint32_t uB = smem_u32(Bh);

    float d[2][4][4];
    #pragma unroll
    for (int mf = 0; mf < 2; mf++)
        #pragma unroll
        for (int nf = 0; nf < 4; nf++)
            #pragma unroll
            for (int e = 0; e < 4; e++) d[mf][nf][e] = 0.f;

    #pragma unroll
    for (int ks = 0; ks < 8; ks++) {
        const int kk = ks * 16;
        uint32_t a[2][4];
        #pragma unroll
        for (int mf = 0; mf < 2; mf++) {
            int row = wm + mf * 16 + (lane & 15);
            int kc  = kk + ((lane >> 4) << 3);
            LDMATRIX_X4(a[mf][0], a[mf][1], a[mf][2], a[mf][3],
                        uA + (uint32_t)(row * HSTRIDE + kc) * 2);
        }
        uint32_t b[4][2];
        #pragma unroll
        for (int np = 0; np < 2; np++) {
            int row = wn + np * 16 + (lane & 7) + ((lane >> 4) << 3);
            int kc  = kk + ((lane & 8) ? 8 : 0);
            uint32_t r0, r1, r2, r3;
            LDMATRIX_X4(r0, r1, r2, r3, uB + (uint32_t)(row * HSTRIDE + kc) * 2);
            b[np*2][0]   = r0; b[np*2][1]   = r1;
            b[np*2+1][0] = r2; b[np*2+1][1] = r3;
        }
        #pragma unroll
        for (int mf = 0; mf < 2; mf++)
            #pragma unroll
            for (int nf = 0; nf < 4; nf++)
                MMA16816(d[mf][nf], a[mf], b[nf]);
    }

    const int g = lane >> 2, t = lane & 3;

    // ---- cross-warp sum-of-squares for row rms (q/k only) ----
    if (midx < 2) {
        #pragma unroll
        for (int mf = 0; mf < 2; mf++) {
            #pragma unroll
            for (int rh = 0; rh < 2; rh++) {
                float p = 0.f;
                #pragma unroll
                for (int nf = 0; nf < 4; nf++)
                    p += d[mf][nf][rh*2]*d[mf][nf][rh*2]
                       + d[mf][nf][rh*2+1]*d[mf][nf][rh*2+1];
                p += __shfl_xor_sync(0xffffffffu, p, 1);
                p += __shfl_xor_sync(0xffffffffu, p, 2);
                if (t == 0)
                    ssred[wm + mf*16 + rh*8 + g][wid >> 1] = p;
            }
        }
    }
    __syncthreads();

    // ---- register-direct epilogue ----
    if (midx < 2) {
        #pragma unroll
        for (int mf = 0; mf < 2; mf++) {
            #pragma unroll
            for (int rh = 0; rh < 2; rh++) {
                int rloc = wm + mf*16 + rh*8 + g;
                float sa = ssred[rloc][0] + ssred[rloc][1]
                         + ssred[rloc][2] + ssred[rloc][3];
                float s = rsqrtf(sa * (1.0f / CDIM) + 1e-5f);
                size_t orow = (size_t)(rowBase + rloc) * CDIM;
                #pragma unroll
                for (int nf = 0; nf < 4; nf++) {
                    int col = wn + nf*8 + t*2;
                    float v0 = d[mf][nf][rh*2]   * s * lnw_s[col];
                    float v1 = d[mf][nf][rh*2+1] * s * lnw_s[col+1];
                    if (midx == 0) {
                        float2 o = {v0, v1};
                        *(float2*)(g_q + orow + col) = o;
                    } else {
                        __half2 hv = __floats2half2_rn(v0, v1);
                        *(unsigned*)(g_kh + orow + col) = *(unsigned*)&hv;
                    }
                }
            }
        }
    } else if (midx == 2) {
        #pragma unroll
        for (int mf = 0; mf < 2; mf++)
            #pragma unroll
            for (int rh = 0; rh < 2; rh++) {
                size_t orow = (size_t)(rowBase + wm + mf*16 + rh*8 + g) * CDIM;
                #pragma unroll
                for (int nf = 0; nf < 4; nf++) {
                    int col = wn + nf*8 + t*2;
                    __half2 hv = __floats2half2_rn(d[mf][nf][rh*2], d[mf][nf][rh*2+1]);
                    *(unsigned*)(g_vh + orow + col) = *(unsigned*)&hv;
                }
            }
    } else {
        #pragma unroll
        for (int mf = 0; mf < 2; mf++)
            #pragma unroll
            for (int rh = 0; rh < 2; rh++) {
                size_t orow = (size_t)(rowBase + wm + mf*16 + rh*8 + g) * CDIM;
                #pragma unroll
                for (int nf = 0; nf < 4; nf++) {
                    int col = wn + nf*8 + t*2;
                    float2 o;
                    o.x = 1.0f / (1.0f + __expf(-d[mf][nf][rh*2]));
                    o.y = 1.0f / (1.0f + __expf(-d[mf][nf][rh*2+1]));
                    *(float2*)(g_g + orow + col) = o;
                }
            }
    }
}

// ============================================================
// K2: attention (unchanged). One block (256 thr) per query row.
// ============================================================
__global__ void __launch_bounds__(256) attn_kernel(
    const float* __restrict__ P, const int* __restrict__ idxg,
    const float* __restrict__ Wb)
{
    __shared__ int   idx_s[KNN];
    __shared__ float q_s[CDIM];
    __shared__ float wb_s[NH*CP];
    __shared__ float bias_s[NH][KNN];
    __shared__ float sc[NH][KNN];
    __shared__ float av_red[4][CDIM];

    const int l = blockIdx.x;
    const int t = threadIdx.x;
    const int w = t >> 5, lane = t & 31;

    if (t < KNN) {
        idx_s[t] = idxg[(size_t)l * KNN + t];
        q_s[t]   = g_q[(size_t)l * CDIM + t] * 0.17677669529663687f;
    }
    if (t < NH*CP) wb_s[t] = Wb[t];
    __syncthreads();

    int jP = (w << 4) + (lane >> 1);
    int pp = lane & 1;
    const float* pr = P + ((size_t)l * LQ + idx_s[jP]) * CP + pp * 8;
    float4 p0 = ((const float4*)pr)[0];
    float4 p1 = ((const float4*)pr)[1];

    {
        const int head = lane >> 3;
        float4 qf = *(const float4*)&q_s[lane * 4];
        #pragma unroll
        for (int b = 0; b < 2; b++) {
            uint2 kb[8];
            #pragma unroll
            for (int i = 0; i < 8; i++) {
                int j = (w << 4) + b * 8 + i;
                kb[i] = ((const uint2*)(g_kh + (size_t)idx_s[j] * CDIM))[lane];
            }
            #pragma unroll
            for (int i = 0; i < 8; i++) {
                int j = (w << 4) + b * 8 + i;
                float2 k0 = __half22float2(*(__half2*)&kb[i].x);
                float2 k1 = __half22float2(*(__half2*)&kb[i].y);
                float d = qf.x*k0.x + qf.y*k0.y + qf.z*k1.x + qf.w*k1.y;
                d += __shfl_down_sync(0xffffffffu, d, 4, 8);
                d += __shfl_down_sync(0xffffffffu, d, 2, 8);
                d += __shfl_down_sync(0xffffffffu, d, 1, 8);
                if ((lane & 7) == 0) sc[head][j] = d;
            }
        }
    }

    {
        float pv[8] = {p0.x,p0.y,p0.z,p0.w, p1.x,p1.y,p1.z,p1.w};
        float b[NH];
        #pragma unroll
        for (int h = 0; h < NH; h++) {
            const float* wbp = &wb_s[h*CP + pp*8];
            b[h] = pv[0]*wbp[0] + pv[1]*wbp[1] + pv[2]*wbp[2] + pv[3]*wbp[3]
                 + pv[4]*wbp[4] + pv[5]*wbp[5] + pv[6]*wbp[6] + pv[7]*wbp[7];
        }
        #pragma unroll
        for (int h = 0; h < NH; h++) {
            b[h] += __shfl_xor_sync(0xffffffffu, b[h], 1);
            if (pp == 0) bias_s[h][jP] = b[h];
        }
    }
    __syncthreads();

    if (t < 128) {
        int h = w;
        float s0 = sc[h][lane]    + bias_s[h][lane];
        float s1 = sc[h][lane+32] + bias_s[h][lane+32];
        float s2 = sc[h][lane+64] + bias_s[h][lane+64];
        float s3 = sc[h][lane+96] + bias_s[h][lane+96];
        float mx = fmaxf(fmaxf(s0, s1), fmaxf(s2, s3));
        #pragma unroll
        for (int o = 16; o; o >>= 1) mx = fmaxf(mx, __shfl_xor_sync(0xffffffffu, mx, o));
        float e0 = __expf(s0 - mx), e1 = __expf(s1 - mx),
              e2 = __expf(s2 - mx), e3 = __expf(s3 - mx);
        float sum = e0 + e1 + e2 + e3;
        #pragma unroll
        for (int o = 16; o; o >>= 1) sum += __shfl_xor_sync(0xffffffffu, sum, o);
        float inv = 1.0f / sum;
        sc[h][lane]    = e0 * inv;
        sc[h][lane+32] = e1 * inv;
        sc[h][lane+64] = e2 * inv;
        sc[h][lane+96] = e3 * inv;
    }
    __syncthreads();

    {
        const int d2 = t & 63;
        const int jg = t >> 6;
        const int h  = d2 >> 4;
        float ax = 0.f, ay = 0.f;
        const unsigned* vbase = (const unsigned*)g_vh;
        #pragma unroll
        for (int b = 0; b < 4; b++) {
            unsigned vb[8];
            #pragma unroll
            for (int i = 0; i < 8; i++) {
                int j = jg * 32 + b * 8 + i;
                vb[i] = vbase[(size_t)idx_s[j] * (CDIM/2) + d2];
            }
            #pragma unroll
            for (int i = 0; i < 8; i++) {
                int j = jg * 32 + b * 8 + i;
                float2 vf = __half22float2(*(__half2*)&vb[i]);
                float p = sc[h][j];
                ax += p * vf.x;
                ay += p * vf.y;
            }
        }
        av_red[jg][2*d2]   = ax;
        av_red[jg][2*d2+1] = ay;
    }
    __syncthreads();
    if (t < CDIM) {
        float o = (av_red[0][t] + av_red[1][t] + av_red[2][t] + av_red[3][t])
                  * g_g[(size_t)l * CDIM + t];
        g_ao[(size_t)l * CDIM + t] = o;
    }
}

// ============================================================
// K3 (split-fp16 HMMA): out = g_ao @ Wo^T. 32-row tiles, grid 128.
// ao = ah + al, Wo = wh + wl; D = ah*wh + al*wh + ah*wl (fp32 acc).
// ============================================================
__global__ void __launch_bounds__(256) out_mma_kernel(
    const float* __restrict__ Wo, float* __restrict__ out)
{
    extern __shared__ __align__(16) char smc[];
    __half* Ah = (__half*)smc;                              // [32][136]
    __half* Al = (__half*)(smc + 32*HSTRIDE*2);
    __half* Wh = (__half*)(smc + 64*HSTRIDE*2);             // [128][136]
    __half* Wl = (__half*)(smc + (64+128)*HSTRIDE*2);

    const int rowBase = blockIdx.x * 32;
    const int tid = threadIdx.x;
    const int wid = tid >> 5, lane = tid & 31;

    // stage A hi/lo: 8 thr/row, 16 cols each
    {
        const int r = tid >> 3, seg = tid & 7;
        const float4* xp = (const float4*)(g_ao + (size_t)(rowBase + r) * CDIM + seg * 16);
        #pragma unroll
        for (int i = 0; i < 4; i++) {
            float4 x = xp[i];
            float vv[4] = {x.x, x.y, x.z, x.w};
            __half hh[4], hl[4];
            #pragma unroll
            for (int e = 0; e < 4; e++) {
                hh[e] = __float2half_rn(vv[e]);
                hl[e] = __float2half_rn(vv[e] - __half2float(hh[e]));
            }
            int off = r * HSTRIDE + seg * 16 + i * 4;
            *(uint2*)(Ah + off) = *(uint2*)hh;
            *(uint2*)(Al + off) = *(uint2*)hl;
        }
    }
    // stage W hi/lo: 2 thr/row, 64 cols each
    {
        const int r = tid >> 1, h = tid & 1;
        const float4* wp = (const float4*)(Wo + (size_t)r * CDIM + h * 64);
        #pragma unroll
        for (int i = 0; i < 16; i++) {
            float4 x = wp[i];
            float vv[4] = {x.x, x.y, x.z, x.w};
            __half hh[4], hl[4];
            #pragma unroll
            for (int e = 0; e < 4; e++) {
                hh[e] = __float2half_rn(vv[e]);
                hl[e] = __float2half_rn(vv[e] - __half2float(hh[e]));
            }
            int off = r * HSTRIDE + h * 64 + i * 4;
            *(uint2*)(Wh + off) = *(uint2*)hh;
            *(uint2*)(Wl + off) = *(uint2*)hl;
        }
    }
    __syncthreads();

    const int wm = (wid & 1) * 16;
    const int wn = (wid >> 1) * 32;
    const uint32_t uAh = smem_u32(Ah), uAl = smem_u32(Al);
    const uint32_t uWh = smem_u32(Wh), uWl = smem_u32(Wl);

    float d[4][4];
    #pragma unroll
    for (int nf = 0; nf < 4; nf++)
        #pragma unroll
        for (int e = 0; e < 4; e++) d[nf][e] = 0.f;

    #pragma unroll
    for (int ks = 0; ks < 8; ks++) {
        const int kk = ks * 16;
        uint32_t aoff = (uint32_t)((wm + (lane & 15)) * HSTRIDE
                                   + kk + ((lane >> 4) << 3)) * 2;
        uint32_t ah[4], al[4];
        LDMATRIX_X4(ah[0], ah[1], ah[2], ah[3], uAh + aoff);
        LDMATRIX_X4(al[0], al[1], al[2], al[3], uAl + aoff);
        uint32_t bh[4][2], bl[4][2];
        #pragma unroll
        for (int np = 0; np < 2; np++) {
            uint32_t boff = (uint32_t)((wn + np*16 + (lane & 7) + ((lane >> 4) << 3)) * HSTRIDE
                                       + kk + ((lane & 8) ? 8 : 0)) * 2;
            uint32_t r0, r1, r2, r3;
            LDMATRIX_X4(r0, r1, r2, r3, uWh + boff);
            bh[np*2][0] = r0; bh[np*2][1] = r1;
            bh[np*2+1][0] = r2; bh[np*2+1][1] = r3;
            LDMATRIX_X4(r0, r1, r2, r3, uWl + boff);
            bl[np*2][0] = r0; bl[np*2][1] = r1;
            bl[np*2+1][0] = r2; bl[np*2+1][1] = r3;
        }
        #pragma unroll
        for (int nf = 0; nf < 4; nf++) {
            MMA16816(d[nf], ah, bh[nf]);
            MMA16816(d[nf], al, bh[nf]);
            MMA16816(d[nf], ah, bl[nf]);
        }
    }

    const int g = lane >> 2, t = lane & 3;
    #pragma unroll
    for (int nf = 0; nf < 4; nf++) {
        int col = wn + nf*8 + t*2;
        size_t r0 = (size_t)(rowBase + wm + g) * CDIM + col;
        size_t r1 = (size_t)(rowBase + wm + g + 8) * CDIM + col;
        float2 o0 = {d[nf][0], d[nf][1]};
        float2 o1 = {d[nf][2], d[nf][3]};
        *(float2*)(out + r0) = o0;
        *(float2*)(out + r1) = o1;
    }
}

// ============================================================
extern "C" void kernel_launch(void* const* d_in, const int* in_sizes, int n_in,
                              void* d_out, int out_size)
{
    const float* Q_L  = (const float*)d_in[0];
    const float* P    = (const float*)d_in[1];
    const int*   idx  = (const int*)  d_in[2];
    const float* Wq   = (const float*)d_in[3];
    const float* Wk   = (const float*)d_in[4];
    const float* Wv   = (const float*)d_in[5];
    const float* Wg   = (const float*)d_in[6];
    const float* Wb   = (const float*)d_in[7];
    const float* Wo   = (const float*)d_in[8];
    const float* ln1  = (const float*)d_in[9];
    const float* lnq  = (const float*)d_in[10];
    const float* lnk  = (const float*)d_in[11];
    float* out = (float*)d_out;

    const int smem_qkvg = (64 + 128) * HSTRIDE * 2;
    const int smem_out  = (32 + 32 + 128 + 128) * HSTRIDE * 2;
    cudaFuncSetAttribute(qkvg_mma_kernel,
        cudaFuncAttributeMaxDynamicSharedMemorySize, smem_qkvg);
    cudaFuncSetAttribute(out_mma_kernel,
        cudaFuncAttributeMaxDynamicSharedMemorySize, smem_out);

    dim3 g1(LQ/64, 4);
    qkvg_mma_kernel<<<g1, 256, smem_qkvg>>>(Q_L, Wq, Wk, Wv, Wg, ln1, lnq, lnk);
    attn_kernel<<<LQ, 256>>>(P, idx, Wb);
    out_mma_kernel<<<LQ/32, 256, smem_out>>>(Wo, out);
}

// round 9
// speedup vs baseline: 1.8647x; 1.1087x over previous
#include <cuda_runtime.h>
#include <cuda_fp16.h>
#include <math.h>
#include <stdint.h>

#define LQ   4096
#define CDIM 128
#define KNN  128
#define NH   4
#define DH   32
#define CP   16

__device__ float  g_q [LQ*CDIM];
__device__ __half g_kh[LQ*CDIM];
__device__ __half g_vh[LQ*CDIM];
__device__ float  g_g [LQ*CDIM];
__device__ float  g_ao[LQ*CDIM];

#define HSTRIDE 136          // fp16 tile row stride (halves)

__device__ __forceinline__ uint32_t smem_u32(const void* p) {
    uint32_t a;
    asm("{ .reg .u64 t; cvta.to.shared.u64 t, %1; cvt.u32.u64 %0, t; }"
        : "=r"(a) : "l"(p));
    return a;
}

#define LDMATRIX_X4(r0, r1, r2, r3, addr) \
    asm volatile("ldmatrix.sync.aligned.m8n8.x4.shared.b16 {%0,%1,%2,%3}, [%4];" \
                 : "=r"(r0), "=r"(r1), "=r"(r2), "=r"(r3) : "r"(addr))

#define MMA16816(d, a, b) \
    asm volatile("mma.sync.aligned.m16n8k16.row.col.f32.f16.f16.f32 " \
                 "{%0,%1,%2,%3}, {%4,%5,%6,%7}, {%8,%9}, {%0,%1,%2,%3};" \
                 : "+f"((d)[0]), "+f"((d)[1]), "+f"((d)[2]), "+f"((d)[3]) \
                 : "r"((a)[0]), "r"((a)[1]), "r"((a)[2]), "r"((a)[3]), \
                   "r"((b)[0]), "r"((b)[1]))

// ============================================================
// K1 (HMMA): fused rms(Q_L) + {q,k,v,g} projection + epilogues.
// grid (64 row-tiles, 4 matrices), 256 thr. (unchanged from R8)
// ============================================================
__global__ void __launch_bounds__(256, 2) qkvg_mma_kernel(
    const float* __restrict__ Q_L,
    const float* __restrict__ Wq, const float* __restrict__ Wk,
    const float* __restrict__ Wv, const float* __restrict__ Wg,
    const float* __restrict__ ln1,
    const float* __restrict__ lnq, const float* __restrict__ lnk)
{
    extern __shared__ __align__(16) char smc[];
    __half* Ah = (__half*)smc;                        // [64][136]
    __half* Bh = (__half*)(smc + 64*HSTRIDE*2);       // [128][136]
    __shared__ float ln1_s[CDIM];
    __shared__ float lnw_s[CDIM];
    __shared__ float ssred[64][5];

    const int midx = blockIdx.y;
    const float* W = (midx == 0) ? Wq : (midx == 1) ? Wk : (midx == 2) ? Wv : Wg;
    const int rowBase = blockIdx.x * 64;
    const int tid  = threadIdx.x;
    const int wid  = tid >> 5, lane = tid & 31;

    if (tid < CDIM) {
        ln1_s[tid] = ln1[tid];
        lnw_s[tid] = (midx == 0) ? lnq[tid] : (midx == 1) ? lnk[tid] : 0.f;
    }
    __syncthreads();

    {
        const int r = tid >> 2, q4 = tid & 3;
        const float4* xp = (const float4*)(Q_L + (size_t)(rowBase + r) * CDIM + q4 * 32);
        float4 xv[8];
        float ss = 0.f;
        #pragma unroll
        for (int i = 0; i < 8; i++) {
            xv[i] = xp[i];
            ss += xv[i].x*xv[i].x + xv[i].y*xv[i].y
                + xv[i].z*xv[i].z + xv[i].w*xv[i].w;
        }
        ss += __shfl_xor_sync(0xffffffffu, ss, 1);
        ss += __shfl_xor_sync(0xffffffffu, ss, 2);
        float s = rsqrtf(ss * (1.0f / CDIM) + 1e-5f);
        __half* ar = Ah + r * HSTRIDE + q4 * 32;
        #pragma unroll
        for (int i = 0; i < 8; i++) {
            int c = q4 * 32 + i * 4;
            __half2 h0 = __floats2half2_rn(xv[i].x*s*ln1_s[c+0], xv[i].y*s*ln1_s[c+1]);
            __half2 h1 = __floats2half2_rn(xv[i].z*s*ln1_s[c+2], xv[i].w*s*ln1_s[c+3]);
            uint2 u; u.x = *(unsigned*)&h0; u.y = *(unsigned*)&h1;
            *(uint2*)(ar + i * 4) = u;
        }
    }
    {
        const int r = tid >> 1, h = tid & 1;
        const float4* wp = (const float4*)(W + (size_t)r * CDIM + h * 64);
        __half* br = Bh + r * HSTRIDE + h * 64;
        #pragma unroll
        for (int i = 0; i < 16; i++) {
            float4 wv = wp[i];
            __half2 h0 = __floats2half2_rn(wv.x, wv.y);
            __half2 h1 = __floats2half2_rn(wv.z, wv.w);
            uint2 u; u.x = *(unsigned*)&h0; u.y = *(unsigned*)&h1;
            *(uint2*)(br + i * 4) = u;
        }
    }
    __syncthreads();

    const int wm = (wid & 1) * 32;
    const int wn = (wid >> 1) * 32;
    const uint32_t uA = smem_u32(Ah);
    const uint32_t uB = smem_u32(Bh);

    float d[2][4][4];
    #pragma unroll
    for (int mf = 0; mf < 2; mf++)
        #pragma unroll
        for (int nf = 0; nf < 4; nf++)
            #pragma unroll
            for (int e = 0; e < 4; e++) d[mf][nf][e] = 0.f;

    #pragma unroll
    for (int ks = 0; ks < 8; ks++) {
        const int kk = ks * 16;
        uint32_t a[2][4];
        #pragma unroll
        for (int mf = 0; mf < 2; mf++) {
            int row = wm + mf * 16 + (lane & 15);
            int kc  = kk + ((lane >> 4) << 3);
            LDMATRIX_X4(a[mf][0], a[mf][1], a[mf][2], a[mf][3],
                        uA + (uint32_t)(row * HSTRIDE + kc) * 2);
        }
        uint32_t b[4][2];
        #pragma unroll
        for (int np = 0; np < 2; np++) {
            int row = wn + np * 16 + (lane & 7) + ((lane >> 4) << 3);
            int kc  = kk + ((lane & 8) ? 8 : 0);
            uint32_t r0, r1, r2, r3;
            LDMATRIX_X4(r0, r1, r2, r3, uB + (uint32_t)(row * HSTRIDE + kc) * 2);
            b[np*2][0]   = r0; b[np*2][1]   = r1;
            b[np*2+1][0] = r2; b[np*2+1][1] = r3;
        }
        #pragma unroll
        for (int mf = 0; mf < 2; mf++)
            #pragma unroll
            for (int nf = 0; nf < 4; nf++)
                MMA16816(d[mf][nf], a[mf], b[nf]);
    }

    const int g = lane >> 2, t = lane & 3;

    if (midx < 2) {
        #pragma unroll
        for (int mf = 0; mf < 2; mf++) {
            #pragma unroll
            for (int rh = 0; rh < 2; rh++) {
                float p = 0.f;
                #pragma unroll
                for (int nf = 0; nf < 4; nf++)
                    p += d[mf][nf][rh*2]*d[mf][nf][rh*2]
                       + d[mf][nf][rh*2+1]*d[mf][nf][rh*2+1];
                p += __shfl_xor_sync(0xffffffffu, p, 1);
                p += __shfl_xor_sync(0xffffffffu, p, 2);
                if (t == 0)
                    ssred[wm + mf*16 + rh*8 + g][wid >> 1] = p;
            }
        }
    }
    __syncthreads();

    if (midx < 2) {
        #pragma unroll
        for (int mf = 0; mf < 2; mf++) {
            #pragma unroll
            for (int rh = 0; rh < 2; rh++) {
                int rloc = wm + mf*16 + rh*8 + g;
                float sa = ssred[rloc][0] + ssred[rloc][1]
                         + ssred[rloc][2] + ssred[rloc][3];
                float s = rsqrtf(sa * (1.0f / CDIM) + 1e-5f);
                size_t orow = (size_t)(rowBase + rloc) * CDIM;
                #pragma unroll
                for (int nf = 0; nf < 4; nf++) {
                    int col = wn + nf*8 + t*2;
                    float v0 = d[mf][nf][rh*2]   * s * lnw_s[col];
                    float v1 = d[mf][nf][rh*2+1] * s * lnw_s[col+1];
                    if (midx == 0) {
                        float2 o = {v0, v1};
                        *(float2*)(g_q + orow + col) = o;
                    } else {
                        __half2 hv = __floats2half2_rn(v0, v1);
                        *(unsigned*)(g_kh + orow + col) = *(unsigned*)&hv;
                    }
                }
            }
        }
    } else if (midx == 2) {
        #pragma unroll
        for (int mf = 0; mf < 2; mf++)
            #pragma unroll
            for (int rh = 0; rh < 2; rh++) {
                size_t orow = (size_t)(rowBase + wm + mf*16 + rh*8 + g) * CDIM;
                #pragma unroll
                for (int nf = 0; nf < 4; nf++) {
                    int col = wn + nf*8 + t*2;
                    __half2 hv = __floats2half2_rn(d[mf][nf][rh*2], d[mf][nf][rh*2+1]);
                    *(unsigned*)(g_vh + orow + col) = *(unsigned*)&hv;
                }
            }
    } else {
        #pragma unroll
        for (int mf = 0; mf < 2; mf++)
            #pragma unroll
            for (int rh = 0; rh < 2; rh++) {
                size_t orow = (size_t)(rowBase + wm + mf*16 + rh*8 + g) * CDIM;
                #pragma unroll
                for (int nf = 0; nf < 4; nf++) {
                    int col = wn + nf*8 + t*2;
                    float2 o;
                    o.x = 1.0f / (1.0f + __expf(-d[mf][nf][rh*2]));
                    o.y = 1.0f / (1.0f + __expf(-d[mf][nf][rh*2+1]));
                    *(float2*)(g_g + orow + col) = o;
                }
            }
    }
}

// ============================================================
// K2: attention — LDG.128 everywhere. One block (256) per row.
// ============================================================
__global__ void __launch_bounds__(256) attn_kernel(
    const float* __restrict__ P, const int* __restrict__ idxg,
    const float* __restrict__ Wb)
{
    __shared__ int   idx_s[KNN];
    __shared__ float q_s[CDIM];
    __shared__ float wb_s[NH*CP];
    __shared__ float bias_s[NH][KNN];
    __shared__ float sc[NH][KNN];
    __shared__ float av_red[16][CDIM];

    const int l = blockIdx.x;
    const int t = threadIdx.x;
    const int w = t >> 5, lane = t & 31;

    if (t < KNN) {
        idx_s[t] = idxg[(size_t)l * KNN + t];
        q_s[t]   = g_q[(size_t)l * CDIM + t] * 0.17677669529663687f;
    }
    if (t < NH*CP) wb_s[t] = Wb[t];
    __syncthreads();

    // ---- issue P loads (DRAM) first ----
    int jP = (w << 4) + (lane >> 1);
    int pp = lane & 1;
    const float* pr = P + ((size_t)l * LQ + idx_s[jP]) * CP + pp * 8;
    float4 p0 = ((const float4*)pr)[0];
    float4 p1 = ((const float4*)pr)[1];

    // ---- scores: warp w -> keys [w*16, w*16+16); 16 lanes/key ----
    {
        const int half16 = lane >> 4;       // key parity within pair
        const int sub    = lane & 15;       // 8-dim chunk
        const int head   = sub >> 2;
        float qv[8];
        #pragma unroll
        for (int i = 0; i < 8; i++) qv[i] = q_s[sub * 8 + i];

        uint4 kb[8];
        int jb[8];
        #pragma unroll
        for (int r = 0; r < 8; r++) {
            jb[r] = (w << 4) + r * 2 + half16;
            kb[r] = *(const uint4*)(g_kh + (size_t)idx_s[jb[r]] * CDIM + sub * 8);
        }
        #pragma unroll
        for (int r = 0; r < 8; r++) {
            float2 a0 = __half22float2(*(__half2*)&kb[r].x);
            float2 a1 = __half22float2(*(__half2*)&kb[r].y);
            float2 a2 = __half22float2(*(__half2*)&kb[r].z);
            float2 a3 = __half22float2(*(__half2*)&kb[r].w);
            float d = qv[0]*a0.x + qv[1]*a0.y + qv[2]*a1.x + qv[3]*a1.y
                    + qv[4]*a2.x + qv[5]*a2.y + qv[6]*a3.x + qv[7]*a3.y;
            d += __shfl_xor_sync(0xffffffffu, d, 1);
            d += __shfl_xor_sync(0xffffffffu, d, 2);
            if ((lane & 3) == 0) sc[head][jb[r]] = d;
        }
    }

    // ---- pair bias from preloaded P ----
    {
        float pv[8] = {p0.x,p0.y,p0.z,p0.w, p1.x,p1.y,p1.z,p1.w};
        float b[NH];
        #pragma unroll
        for (int h = 0; h < NH; h++) {
            const float* wbp = &wb_s[h*CP + pp*8];
            b[h] = pv[0]*wbp[0] + pv[1]*wbp[1] + pv[2]*wbp[2] + pv[3]*wbp[3]
                 + pv[4]*wbp[4] + pv[5]*wbp[5] + pv[6]*wbp[6] + pv[7]*wbp[7];
        }
        #pragma unroll
        for (int h = 0; h < NH; h++) {
            b[h] += __shfl_xor_sync(0xffffffffu, b[h], 1);
            if (pp == 0) bias_s[h][jP] = b[h];
        }
    }
    __syncthreads();

    // ---- softmax per head (warps 0..3) ----
    if (t < 128) {
        int h = w;
        float s0 = sc[h][lane]    + bias_s[h][lane];
        float s1 = sc[h][lane+32] + bias_s[h][lane+32];
        float s2 = sc[h][lane+64] + bias_s[h][lane+64];
        float s3 = sc[h][lane+96] + bias_s[h][lane+96];
        float mx = fmaxf(fmaxf(s0, s1), fmaxf(s2, s3));
        #pragma unroll
        for (int o = 16; o; o >>= 1) mx = fmaxf(mx, __shfl_xor_sync(0xffffffffu, mx, o));
        float e0 = __expf(s0 - mx), e1 = __expf(s1 - mx),
              e2 = __expf(s2 - mx), e3 = __expf(s3 - mx);
        float sum = e0 + e1 + e2 + e3;
        #pragma unroll
        for (int o = 16; o; o >>= 1) sum += __shfl_xor_sync(0xffffffffu, sum, o);
        float inv = 1.0f / sum;
        sc[h][lane]    = e0 * inv;
        sc[h][lane+32] = e1 * inv;
        sc[h][lane+64] = e2 * inv;
        sc[h][lane+96] = e3 * inv;
    }
    __syncthreads();

    // ---- AV: thread = (8-dim chunk d8, 8-key group jg) ----
    {
        const int d8 = t & 15;
        const int jg = t >> 4;
        const int h  = d8 >> 2;
        uint4 vb[8];
        #pragma unroll
        for (int i = 0; i < 8; i++)
            vb[i] = *(const uint4*)(g_vh + (size_t)idx_s[jg*8 + i] * CDIM + d8 * 8);
        float acc[8] = {0,0,0,0,0,0,0,0};
        #pragma unroll
        for (int i = 0; i < 8; i++) {
            float p = sc[h][jg*8 + i];
            float2 v0 = __half22float2(*(__half2*)&vb[i].x);
            float2 v1 = __half22float2(*(__half2*)&vb[i].y);
            float2 v2 = __half22float2(*(__half2*)&vb[i].z);
            float2 v3 = __half22float2(*(__half2*)&vb[i].w);
            acc[0] += p*v0.x; acc[1] += p*v0.y;
            acc[2] += p*v1.x; acc[3] += p*v1.y;
            acc[4] += p*v2.x; acc[5] += p*v2.y;
            acc[6] += p*v3.x; acc[7] += p*v3.y;
        }
        float4 o0 = {acc[0], acc[1], acc[2], acc[3]};
        float4 o1 = {acc[4], acc[5], acc[6], acc[7]};
        *(float4*)&av_red[jg][d8*8]     = o0;
        *(float4*)&av_red[jg][d8*8 + 4] = o1;
    }
    __syncthreads();
    if (t < CDIM) {
        float o = 0.f;
        #pragma unroll
        for (int jg2 = 0; jg2 < 16; jg2++) o += av_red[jg2][t];
        o *= g_g[(size_t)l * CDIM + t];
        g_ao[(size_t)l * CDIM + t] = o;
    }
}

// ============================================================
// K3 (split-fp16 HMMA): out = g_ao @ Wo^T. (unchanged from R8)
// ============================================================
__global__ void __launch_bounds__(256) out_mma_kernel(
    const float* __restrict__ Wo, float* __restrict__ out)
{
    extern __shared__ __align__(16) char smc[];
    __half* Ah = (__half*)smc;
    __half* Al = (__half*)(smc + 32*HSTRIDE*2);
    __half* Wh = (__half*)(smc + 64*HSTRIDE*2);
    __half* Wl = (__half*)(smc + (64+128)*HSTRIDE*2);

    const int rowBase = blockIdx.x * 32;
    const int tid = threadIdx.x;
    const int wid = tid >> 5, lane = tid & 31;

    {
        const int r = tid >> 3, seg = tid & 7;
        const float4* xp = (const float4*)(g_ao + (size_t)(rowBase + r) * CDIM + seg * 16);
        #pragma unroll
        for (int i = 0; i < 4; i++) {
            float4 x = xp[i];
            float vv[4] = {x.x, x.y, x.z, x.w};
            __half hh[4], hl[4];
            #pragma unroll
            for (int e = 0; e < 4; e++) {
                hh[e] = __float2half_rn(vv[e]);
                hl[e] = __float2half_rn(vv[e] - __half2float(hh[e]));
            }
            int off = r * HSTRIDE + seg * 16 + i * 4;
            *(uint2*)(Ah + off) = *(uint2*)hh;
            *(uint2*)(Al + off) = *(uint2*)hl;
        }
    }
    {
        const int r = tid >> 1, h = tid & 1;
        const float4* wp = (const float4*)(Wo + (size_t)r * CDIM + h * 64);
        #pragma unroll
        for (int i = 0; i < 16; i++) {
            float4 x = wp[i];
            float vv[4] = {x.x, x.y, x.z, x.w};
            __half hh[4], hl[4];
            #pragma unroll
            for (int e = 0; e < 4; e++) {
                hh[e] = __float2half_rn(vv[e]);
                hl[e] = __float2half_rn(vv[e] - __half2float(hh[e]));
            }
            int off = r * HSTRIDE + h * 64 + i * 4;
            *(uint2*)(Wh + off) = *(uint2*)hh;
            *(uint2*)(Wl + off) = *(uint2*)hl;
        }
    }
    __syncthreads();

    const int wm = (wid & 1) * 16;
    const int wn = (wid >> 1) * 32;
    const uint32_t uAh = smem_u32(Ah), uAl = smem_u32(Al);
    const uint32_t uWh = smem_u32(Wh), uWl = smem_u32(Wl);

    float d[4][4];
    #pragma unroll
    for (int nf = 0; nf < 4; nf++)
        #pragma unroll
        for (int e = 0; e < 4; e++) d[nf][e] = 0.f;

    #pragma unroll
    for (int ks = 0; ks < 8; ks++) {
        const int kk = ks * 16;
        uint32_t aoff = (uint32_t)((wm + (lane & 15)) * HSTRIDE
                                   + kk + ((lane >> 4) << 3)) * 2;
        uint32_t ah[4], al[4];
        LDMATRIX_X4(ah[0], ah[1], ah[2], ah[3], uAh + aoff);
        LDMATRIX_X4(al[0], al[1], al[2], al[3], uAl + aoff);
        uint32_t bh[4][2], bl[4][2];
        #pragma unroll
        for (int np = 0; np < 2; np++) {
            uint32_t boff = (uint32_t)((wn + np*16 + (lane & 7) + ((lane >> 4) << 3)) * HSTRIDE
                                       + kk + ((lane & 8) ? 8 : 0)) * 2;
            uint32_t r0, r1, r2, r3;
            LDMATRIX_X4(r0, r1, r2, r3, uWh + boff);
            bh[np*2][0] = r0; bh[np*2][1] = r1;
            bh[np*2+1][0] = r2; bh[np*2+1][1] = r3;
            LDMATRIX_X4(r0, r1, r2, r3, uWl + boff);
            bl[np*2][0] = r0; bl[np*2][1] = r1;
            bl[np*2+1][0] = r2; bl[np*2+1][1] = r3;
        }
        #pragma unroll
        for (int nf = 0; nf < 4; nf++) {
            MMA16816(d[nf], ah, bh[nf]);
            MMA16816(d[nf], al, bh[nf]);
            MMA16816(d[nf], ah, bl[nf]);
        }
    }

    const int g = lane >> 2, t = lane & 3;
    #pragma unroll
    for (int nf = 0; nf < 4; nf++) {
        int col = wn + nf*8 + t*2;
        size_t r0 = (size_t)(rowBase + wm + g) * CDIM + col;
        size_t r1 = (size_t)(rowBase + wm + g + 8) * CDIM + col;
        float2 o0 = {d[nf][0], d[nf][1]};
        float2 o1 = {d[nf][2], d[nf][3]};
        *(float2*)(out + r0) = o0;
        *(float2*)(out + r1) = o1;
    }
}

// ============================================================
extern "C" void kernel_launch(void* const* d_in, const int* in_sizes, int n_in,
                              void* d_out, int out_size)
{
    const float* Q_L  = (const float*)d_in[0];
    const float* P    = (const float*)d_in[1];
    const int*   idx  = (const int*)  d_in[2];
    const float* Wq   = (const float*)d_in[3];
    const float* Wk   = (const float*)d_in[4];
    const float* Wv   = (const float*)d_in[5];
    const float* Wg   = (const float*)d_in[6];
    const float* Wb   = (const float*)d_in[7];
    const float* Wo   = (const float*)d_in[8];
    const float* ln1  = (const float*)d_in[9];
    const float* lnq  = (const float*)d_in[10];
    const float* lnk  = (const float*)d_in[11];
    float* out = (float*)d_out;

    const int smem_qkvg = (64 + 128) * HSTRIDE * 2;
    const int smem_out  = (32 + 32 + 128 + 128) * HSTRIDE * 2;
    cudaFuncSetAttribute(qkvg_mma_kernel,
        cudaFuncAttributeMaxDynamicSharedMemorySize, smem_qkvg);
    cudaFuncSetAttribute(out_mma_kernel,
        cudaFuncAttributeMaxDynamicSharedMemorySize, smem_out);

    dim3 g1(LQ/64, 4);
    qkvg_mma_kernel<<<g1, 256, smem_qkvg>>>(Q_L, Wq, Wk, Wv, Wg, ln1, lnq, lnk);
    attn_kernel<<<LQ, 256>>>(P, idx, Wb);
    out_mma_kernel<<<LQ/32, 256, smem_out>>>(Wo, out);
}